// round 1
// baseline (speedup 1.0000x reference)
#include <cuda_runtime.h>
#include <cuda_bf16.h>
#include <cstdint>
#include <math.h>

// ---------------- problem constants (from reference) ----------------
#define NNODES 50000
#define F_IN   512
#define H0     256
#define H1     128
#define H2     128
#define NCLS   40
#define DFIN   768   // H0 + 2*H1 + 2*H2

// ---------------- static scratch (no allocs allowed) ----------------
__device__ float g_h[(size_t)NNODES * H0];        // relu(x@W1+b1)
__device__ float g_hw[(size_t)NNODES * H1];       // h@Wc1, then r1@Wc2
__device__ float g_agg_a[(size_t)NNODES * H1];    // per-edge-set aggregates
__device__ float g_agg_b[(size_t)NNODES * H1];
__device__ float g_r1[(size_t)NNODES * (2 * H1)];
__device__ float g_final[(size_t)NNODES * DFIN];
__device__ float g_logits[(size_t)NNODES * NCLS];
__device__ float g_deg1[NNODES];
__device__ float g_deg2[NNODES];
__device__ float g_dis1[NNODES];
__device__ float g_dis2[NNODES];

// ---------------- utility kernels ----------------
__global__ void zero_kernel(float* __restrict__ p, size_t n4) {
    // n4 = count of float4s
    size_t i = (size_t)blockIdx.x * blockDim.x + threadIdx.x;
    size_t stride = (size_t)gridDim.x * blockDim.x;
    float4 z = make_float4(0.f, 0.f, 0.f, 0.f);
    for (; i < n4; i += stride) reinterpret_cast<float4*>(p)[i] = z;
}

__global__ void deg_kernel(const int* __restrict__ ei, int E, float* __restrict__ deg) {
    int e = blockIdx.x * blockDim.x + threadIdx.x;
    if (e < E) atomicAdd(&deg[ei[E + e]], 1.0f);
}

__global__ void dis_kernel(const float* __restrict__ deg, float* __restrict__ dis, int n) {
    int i = blockIdx.x * blockDim.x + threadIdx.x;
    if (i < n) {
        float d = deg[i];
        dis[i] = (d > 0.f) ? rsqrtf(d) : 0.f;
    }
}

// ---------------- tiled SGEMM: C[M,N] = op(A[M,K] @ B[K,N] + bias) ----------------
// BM=BN=64, BK=16, thread tile 4x4, 256 threads. Requires K % 16 == 0, N % 4 == 0.
template <bool RELU, bool BIAS>
__global__ void sgemm_kernel(const float* __restrict__ A, const float* __restrict__ B,
                             const float* __restrict__ bias, float* __restrict__ C,
                             int M, int N, int K) {
    __shared__ float As[16][64];   // k-major
    __shared__ float Bs[16][64];

    const int tx = threadIdx.x;        // 0..15 -> N
    const int ty = threadIdx.y;        // 0..15 -> M
    const int tid = ty * 16 + tx;      // 0..255
    const int bm0 = blockIdx.y * 64;
    const int bn0 = blockIdx.x * 64;

    // A-load mapping: each thread loads one float4 (row tid/4, k-quad tid%4)
    const int aRow = tid >> 2;          // 0..63
    const int aK4  = (tid & 3) * 4;     // 0,4,8,12
    // B-load mapping: row tid/16 (0..15), col-quad tid%16
    const int bRow = tid >> 4;          // 0..15
    const int bC4  = (tid & 15) * 4;    // 0..60

    float acc[4][4];
#pragma unroll
    for (int i = 0; i < 4; i++)
#pragma unroll
        for (int j = 0; j < 4; j++) acc[i][j] = 0.f;

    const int gAr = bm0 + aRow;
    const bool aValid = (gAr < M);
    const int gBc = bn0 + bC4;
    const bool bValid = (gBc < N);     // N % 4 == 0 and gBc % 4 == 0 => full float4 in-range

    for (int k0 = 0; k0 < K; k0 += 16) {
        float4 av = make_float4(0.f, 0.f, 0.f, 0.f);
        if (aValid) av = *reinterpret_cast<const float4*>(A + (size_t)gAr * K + k0 + aK4);
        As[aK4 + 0][aRow] = av.x;
        As[aK4 + 1][aRow] = av.y;
        As[aK4 + 2][aRow] = av.z;
        As[aK4 + 3][aRow] = av.w;

        float4 bv = make_float4(0.f, 0.f, 0.f, 0.f);
        if (bValid) bv = *reinterpret_cast<const float4*>(B + (size_t)(k0 + bRow) * N + gBc);
        Bs[bRow][bC4 + 0] = bv.x;
        Bs[bRow][bC4 + 1] = bv.y;
        Bs[bRow][bC4 + 2] = bv.z;
        Bs[bRow][bC4 + 3] = bv.w;

        __syncthreads();

#pragma unroll
        for (int k = 0; k < 16; k++) {
            float4 a4 = *reinterpret_cast<const float4*>(&As[k][ty * 4]);
            float4 b4 = *reinterpret_cast<const float4*>(&Bs[k][tx * 4]);
            const float ar[4] = {a4.x, a4.y, a4.z, a4.w};
            const float br[4] = {b4.x, b4.y, b4.z, b4.w};
#pragma unroll
            for (int i = 0; i < 4; i++)
#pragma unroll
                for (int j = 0; j < 4; j++) acc[i][j] = fmaf(ar[i], br[j], acc[i][j]);
        }
        __syncthreads();
    }

    const int colBase = bn0 + tx * 4;
    float bv[4] = {0.f, 0.f, 0.f, 0.f};
    if (BIAS && colBase < N) {
        float4 t = *reinterpret_cast<const float4*>(bias + colBase);
        bv[0] = t.x; bv[1] = t.y; bv[2] = t.z; bv[3] = t.w;
    }
#pragma unroll
    for (int i = 0; i < 4; i++) {
        int row = bm0 + ty * 4 + i;
        if (row < M && colBase < N) {
            float4 o;
            float v0 = acc[i][0] + bv[0];
            float v1 = acc[i][1] + bv[1];
            float v2 = acc[i][2] + bv[2];
            float v3 = acc[i][3] + bv[3];
            if (RELU) {
                v0 = fmaxf(v0, 0.f); v1 = fmaxf(v1, 0.f);
                v2 = fmaxf(v2, 0.f); v3 = fmaxf(v3, 0.f);
            }
            o.x = v0; o.y = v1; o.z = v2; o.w = v3;
            *reinterpret_cast<float4*>(C + (size_t)row * N + colBase) = o;
        }
    }
}

// ---------------- edge scatter: agg[col] += src[row] * dis[row]*dis[col] ----------------
// one warp per edge, 128 floats per edge -> 1 float4 per lane
__global__ void scatter_kernel(const int* __restrict__ ei, int E,
                               const float* __restrict__ dis,
                               const float* __restrict__ src,
                               float* __restrict__ agg) {
    int warp = (blockIdx.x * blockDim.x + threadIdx.x) >> 5;
    int lane = threadIdx.x & 31;
    if (warp >= E) return;
    int r = ei[warp];
    int c = ei[E + warp];
    float nrm = dis[r] * dis[c];
    if (nrm == 0.f) return;
    float4 v = *reinterpret_cast<const float4*>(src + (size_t)r * 128 + lane * 4);
    float x = v.x * nrm, y = v.y * nrm, z = v.z * nrm, w = v.w * nrm;
    float* dst = agg + (size_t)c * 128 + lane * 4;
    asm volatile("red.global.add.v4.f32 [%0], {%1,%2,%3,%4};"
                 :: "l"(dst), "f"(x), "f"(y), "f"(z), "f"(w) : "memory");
}

// ---------------- assemble R1 (+bias) into r1 and final[:,0:512] ----------------
__global__ void build_r1_kernel(const float* __restrict__ agg_a, const float* __restrict__ agg_b,
                                const float* __restrict__ b_c1, const float* __restrict__ h,
                                float* __restrict__ r1, float* __restrict__ fin, int n) {
    size_t total = (size_t)n * 128;
    size_t stride = (size_t)gridDim.x * blockDim.x;
    for (size_t idx = (size_t)blockIdx.x * blockDim.x + threadIdx.x; idx < total; idx += stride) {
        size_t i = idx >> 7;
        int j = (int)(idx & 127);
        float va = agg_a[idx] + b_c1[j];
        float vb = agg_b[idx] + b_c1[j];
        r1[i * 256 + j]        = va;
        r1[i * 256 + 128 + j]  = vb;
        fin[i * DFIN + 256 + j] = va;
        fin[i * DFIN + 384 + j] = vb;
    }
    size_t total2 = (size_t)n * 256;
    for (size_t idx = (size_t)blockIdx.x * blockDim.x + threadIdx.x; idx < total2; idx += stride) {
        size_t i = idx >> 8;
        int j = (int)(idx & 255);
        fin[i * DFIN + j] = h[idx];
    }
}

// ---------------- assemble R2 (+bias) into final[:,512:768] ----------------
__global__ void build_r2_kernel(const float* __restrict__ agg_a, const float* __restrict__ agg_b,
                                const float* __restrict__ b_c2, float* __restrict__ fin, int n) {
    size_t total = (size_t)n * 128;
    size_t stride = (size_t)gridDim.x * blockDim.x;
    for (size_t idx = (size_t)blockIdx.x * blockDim.x + threadIdx.x; idx < total; idx += stride) {
        size_t i = idx >> 7;
        int j = (int)(idx & 127);
        fin[i * DFIN + 512 + j] = agg_a[idx] + b_c2[j];
        fin[i * DFIN + 640 + j] = agg_b[idx] + b_c2[j];
    }
}

// ---------------- log_softmax over 40 logits, one warp per row ----------------
__global__ void logsoftmax_kernel(const float* __restrict__ logits, float* __restrict__ out, int M) {
    int warp = (blockIdx.x * blockDim.x + threadIdx.x) >> 5;
    int lane = threadIdx.x & 31;
    if (warp >= M) return;
    const float* L = logits + (size_t)warp * NCLS;
    float v0 = L[lane];                                   // lanes 0..31 valid (<40)
    float v1 = (lane < NCLS - 32) ? L[32 + lane] : -INFINITY;
    float m = fmaxf(v0, v1);
#pragma unroll
    for (int o = 16; o > 0; o >>= 1) m = fmaxf(m, __shfl_xor_sync(0xffffffffu, m, o));
    float s = expf(v0 - m) + ((lane < NCLS - 32) ? expf(v1 - m) : 0.f);
#pragma unroll
    for (int o = 16; o > 0; o >>= 1) s += __shfl_xor_sync(0xffffffffu, s, o);
    float ls = logf(s);
    float* O = out + (size_t)warp * NCLS;
    O[lane] = v0 - m - ls;
    if (lane < NCLS - 32) O[32 + lane] = v1 - m - ls;
}

// ---------------- host launcher ----------------
extern "C" void kernel_launch(void* const* d_in, const int* in_sizes, int n_in,
                              void* d_out, int out_size) {
    const float* x       = (const float*)d_in[0];
    const int*   ei1     = (const int*)  d_in[1];
    const int*   ei2     = (const int*)  d_in[2];
    const float* W_lin1  = (const float*)d_in[3];
    const float* b_lin1  = (const float*)d_in[4];
    const float* W_c1    = (const float*)d_in[5];
    const float* b_c1    = (const float*)d_in[6];
    const float* W_c2    = (const float*)d_in[7];
    const float* b_c2    = (const float*)d_in[8];
    const float* W_lin2  = (const float*)d_in[9];
    const float* b_lin2  = (const float*)d_in[10];
    float* out = (float*)d_out;

    const int E1 = in_sizes[1] / 2;
    const int E2 = in_sizes[2] / 2;
    const int n  = NNODES;

    float *p_h, *p_hw, *p_agg_a, *p_agg_b, *p_r1, *p_final, *p_logits;
    float *p_deg1, *p_deg2, *p_dis1, *p_dis2;
    cudaGetSymbolAddress((void**)&p_h,      g_h);
    cudaGetSymbolAddress((void**)&p_hw,     g_hw);
    cudaGetSymbolAddress((void**)&p_agg_a,  g_agg_a);
    cudaGetSymbolAddress((void**)&p_agg_b,  g_agg_b);
    cudaGetSymbolAddress((void**)&p_r1,     g_r1);
    cudaGetSymbolAddress((void**)&p_final,  g_final);
    cudaGetSymbolAddress((void**)&p_logits, g_logits);
    cudaGetSymbolAddress((void**)&p_deg1,   g_deg1);
    cudaGetSymbolAddress((void**)&p_deg2,   g_deg2);
    cudaGetSymbolAddress((void**)&p_dis1,   g_dis1);
    cudaGetSymbolAddress((void**)&p_dis2,   g_dis2);

    const dim3 blk2d(16, 16);

    // --- zero degree + aggregate buffers ---
    zero_kernel<<<512, 256>>>(p_deg1, NNODES / 4);
    zero_kernel<<<512, 256>>>(p_deg2, NNODES / 4);
    zero_kernel<<<2048, 256>>>(p_agg_a, (size_t)n * 128 / 4);
    zero_kernel<<<2048, 256>>>(p_agg_b, (size_t)n * 128 / 4);

    // --- degrees & normalization ---
    deg_kernel<<<(E1 + 255) / 256, 256>>>(ei1, E1, p_deg1);
    deg_kernel<<<(E2 + 255) / 256, 256>>>(ei2, E2, p_deg2);
    dis_kernel<<<(n + 255) / 256, 256>>>(p_deg1, p_dis1, n);
    dis_kernel<<<(n + 255) / 256, 256>>>(p_deg2, p_dis2, n);

    // --- h = relu(x @ W_lin1 + b_lin1)  [50000,512]x[512,256] ---
    {
        dim3 grid((H0 + 63) / 64, (n + 63) / 64);
        sgemm_kernel<true, true><<<grid, blk2d>>>(x, W_lin1, b_lin1, p_h, n, H0, F_IN);
    }
    // --- hw = h @ W_c1 (shared by both edge sets)  [50000,256]x[256,128] ---
    {
        dim3 grid((H1 + 63) / 64, (n + 63) / 64);
        sgemm_kernel<false, false><<<grid, blk2d>>>(p_h, W_c1, nullptr, p_hw, n, H1, H0);
    }
    // --- layer-1 scatters ---
    scatter_kernel<<<(E1 + 7) / 8, 256>>>(ei1, E1, p_dis1, p_hw, p_agg_a);
    scatter_kernel<<<(E2 + 7) / 8, 256>>>(ei2, E2, p_dis2, p_hw, p_agg_b);

    // --- R1 = [agg_a+b, agg_b+b]; also fill final[:,0:512] ---
    build_r1_kernel<<<2048, 256>>>(p_agg_a, p_agg_b, b_c1, p_h, p_r1, p_final, n);

    // --- re-zero aggregates for layer 2 ---
    zero_kernel<<<2048, 256>>>(p_agg_a, (size_t)n * 128 / 4);
    zero_kernel<<<2048, 256>>>(p_agg_b, (size_t)n * 128 / 4);

    // --- hw = R1 @ W_c2  [50000,256]x[256,128] ---
    {
        dim3 grid((H2 + 63) / 64, (n + 63) / 64);
        sgemm_kernel<false, false><<<grid, blk2d>>>(p_r1, W_c2, nullptr, p_hw, n, H2, 2 * H1);
    }
    // --- layer-2 scatters ---
    scatter_kernel<<<(E1 + 7) / 8, 256>>>(ei1, E1, p_dis1, p_hw, p_agg_a);
    scatter_kernel<<<(E2 + 7) / 8, 256>>>(ei2, E2, p_dis2, p_hw, p_agg_b);

    // --- final[:,512:768] = R2 + b_c2 ---
    build_r2_kernel<<<2048, 256>>>(p_agg_a, p_agg_b, b_c2, p_final, n);

    // --- logits = final @ W_lin2 + b_lin2  [50000,768]x[768,40] ---
    {
        dim3 grid((NCLS + 63) / 64, (n + 63) / 64);
        sgemm_kernel<false, true><<<grid, blk2d>>>(p_final, W_lin2, b_lin2, p_logits, n, NCLS, DFIN);
    }
    // --- log_softmax -> out ---
    logsoftmax_kernel<<<(n + 7) / 8, 256>>>(p_logits, out, n);
}

// round 2
// speedup vs baseline: 1.3907x; 1.3907x over previous
#include <cuda_runtime.h>
#include <cuda_bf16.h>
#include <cstdint>
#include <math.h>

// ---------------- problem constants (from reference) ----------------
#define NNODES 50000
#define F_IN   512
#define H0     256
#define H1     128
#define H2     128
#define NCLS   40
#define DFIN   768   // H0 + 2*H1 + 2*H2

// ---------------- static scratch (no allocs allowed) ----------------
__device__ float g_h[(size_t)NNODES * H0];        // relu(x@W1+b1)
__device__ float g_hw[(size_t)NNODES * H1];       // h@Wc1, then r1@Wc2
__device__ float g_agg_a[(size_t)NNODES * H1];    // per-edge-set aggregates
__device__ float g_agg_b[(size_t)NNODES * H1];
__device__ float g_r1[(size_t)NNODES * (2 * H1)];
__device__ float g_final[(size_t)NNODES * DFIN];
__device__ float g_logits[(size_t)NNODES * NCLS];
__device__ float g_deg1[NNODES];
__device__ float g_deg2[NNODES];
__device__ float g_dis1[NNODES];
__device__ float g_dis2[NNODES];

// ---------------- utility kernels ----------------
__global__ void zero_kernel(float* __restrict__ p, size_t n4) {
    size_t i = (size_t)blockIdx.x * blockDim.x + threadIdx.x;
    size_t stride = (size_t)gridDim.x * blockDim.x;
    float4 z = make_float4(0.f, 0.f, 0.f, 0.f);
    for (; i < n4; i += stride) reinterpret_cast<float4*>(p)[i] = z;
}

__global__ void deg_kernel(const int* __restrict__ ei, int E, float* __restrict__ deg) {
    int e = blockIdx.x * blockDim.x + threadIdx.x;
    if (e < E) atomicAdd(&deg[ei[E + e]], 1.0f);
}

__global__ void dis_kernel(const float* __restrict__ deg, float* __restrict__ dis, int n) {
    int i = blockIdx.x * blockDim.x + threadIdx.x;
    if (i < n) {
        float d = deg[i];
        dis[i] = (d > 0.f) ? rsqrtf(d) : 0.f;
    }
}

// ---------------- TF32 helpers ----------------
__device__ __forceinline__ float to_tf32(float x) {
    uint32_t u;
    asm("cvt.rna.tf32.f32 %0, %1;" : "=r"(u) : "f"(x));
    return __uint_as_float(u);
}

__device__ __forceinline__ void mma_tf32(float* c, const uint32_t* a, uint32_t b0, uint32_t b1) {
    asm volatile(
        "mma.sync.aligned.m16n8k8.row.col.f32.tf32.tf32.f32 "
        "{%0,%1,%2,%3}, {%4,%5,%6,%7}, {%8,%9}, {%0,%1,%2,%3};"
        : "+f"(c[0]), "+f"(c[1]), "+f"(c[2]), "+f"(c[3])
        : "r"(a[0]), "r"(a[1]), "r"(a[2]), "r"(a[3]), "r"(b0), "r"(b1));
}

// ---------------- TF32 tensor-core GEMM: C = op(A[M,K] @ B[K,N] + bias) ----------------
// Block tile 128x128, BK=16, 8 warps each computing 64x32 (4x4 m16n8k8 tiles).
// Requires K % 16 == 0, N % 8 == 0.
#define AS_STRIDE 20
#define BS_STRIDE 132
template <bool RELU, bool BIAS>
__global__ __launch_bounds__(256)
void mma_gemm_kernel(const float* __restrict__ A, const float* __restrict__ B,
                     const float* __restrict__ bias, float* __restrict__ C,
                     int M, int N, int K) {
    __shared__ float As[2][128][AS_STRIDE];   // m-major (row-major, 16 k per row)
    __shared__ float Bs[2][16][BS_STRIDE];    // k-major

    const int tid  = threadIdx.x;
    const int lane = tid & 31;
    const int warp = tid >> 5;
    const int bm0 = blockIdx.y * 128;
    const int bn0 = blockIdx.x * 128;
    const int wm = (warp & 1) * 64;   // warp M offset within block
    const int wn = (warp >> 1) * 32;  // warp N offset within block
    const int g  = lane >> 2;         // groupID
    const int tg = lane & 3;          // thread in group

    float acc[4][4][4];
#pragma unroll
    for (int i = 0; i < 4; i++)
#pragma unroll
        for (int j = 0; j < 4; j++)
#pragma unroll
            for (int q = 0; q < 4; q++) acc[i][j][q] = 0.f;

    // A tile load mapping: thread -> row tid/2, half h = tid%2 (8 consecutive floats)
    const int aRow = tid >> 1;
    const int aH   = (tid & 1) * 8;
    const bool aValid = (bm0 + aRow) < M;
    const float* Aptr = A + (size_t)(bm0 + aRow) * K + aH;

    // B tile load mapping: thread loads 2 float4s: rows tid/32 and tid/32+8, col quad (tid%32)*4
    const int bRow = tid >> 5;          // 0..7 (second: +8)
    const int bC4  = (tid & 31) * 4;    // 0..124
    const bool bValid = (bn0 + bC4) < N;   // N%4==0 -> whole float4 in/out
    const float* Bptr = B + (size_t)bRow * N + bn0 + bC4;

    const int ntiles = K / 16;
    const float4 zero4 = make_float4(0.f, 0.f, 0.f, 0.f);

    // ---- prologue: load tile 0 ----
    float4 ra0 = zero4, ra1 = zero4, rb0 = zero4, rb1 = zero4;
    if (aValid) {
        ra0 = *reinterpret_cast<const float4*>(Aptr);
        ra1 = *reinterpret_cast<const float4*>(Aptr + 4);
    }
    if (bValid) {
        rb0 = *reinterpret_cast<const float4*>(Bptr);
        rb1 = *reinterpret_cast<const float4*>(Bptr + (size_t)8 * N);
    }
    {
        float* as = &As[0][aRow][aH];
        as[0] = to_tf32(ra0.x); as[1] = to_tf32(ra0.y); as[2] = to_tf32(ra0.z); as[3] = to_tf32(ra0.w);
        as[4] = to_tf32(ra1.x); as[5] = to_tf32(ra1.y); as[6] = to_tf32(ra1.z); as[7] = to_tf32(ra1.w);
        float* bs0 = &Bs[0][bRow][bC4];
        bs0[0] = to_tf32(rb0.x); bs0[1] = to_tf32(rb0.y); bs0[2] = to_tf32(rb0.z); bs0[3] = to_tf32(rb0.w);
        float* bs1 = &Bs[0][bRow + 8][bC4];
        bs1[0] = to_tf32(rb1.x); bs1[1] = to_tf32(rb1.y); bs1[2] = to_tf32(rb1.z); bs1[3] = to_tf32(rb1.w);
    }
    __syncthreads();

    // ldmatrix source row/col (per-thread) within As
    const int lm_row = wm + (lane & 7) + ((lane >> 3) & 1) * 8;  // + mi*16
    const int lm_kq  = (lane >> 4) * 4;                           // + kk

    int buf = 0;
    for (int t = 1; t <= ntiles; t++) {
        // ---- prefetch next tile into registers ----
        if (t < ntiles) {
            const int k0 = t * 16;
            if (aValid) {
                ra0 = *reinterpret_cast<const float4*>(Aptr + k0);
                ra1 = *reinterpret_cast<const float4*>(Aptr + k0 + 4);
            }
            if (bValid) {
                rb0 = *reinterpret_cast<const float4*>(Bptr + (size_t)k0 * N);
                rb1 = *reinterpret_cast<const float4*>(Bptr + (size_t)(k0 + 8) * N);
            }
        }

        // ---- compute on current buffer ----
#pragma unroll
        for (int kk = 0; kk < 16; kk += 8) {
            uint32_t af[4][4];
#pragma unroll
            for (int mi = 0; mi < 4; mi++) {
                uint32_t saddr = (uint32_t)__cvta_generic_to_shared(
                    &As[buf][lm_row + mi * 16][kk + lm_kq]);
                asm volatile("ldmatrix.sync.aligned.m8n8.x4.shared.b16 {%0,%1,%2,%3}, [%4];"
                             : "=r"(af[mi][0]), "=r"(af[mi][1]), "=r"(af[mi][2]), "=r"(af[mi][3])
                             : "r"(saddr));
            }
#pragma unroll
            for (int nj = 0; nj < 4; nj++) {
                uint32_t b0 = __float_as_uint(Bs[buf][kk + tg][wn + nj * 8 + g]);
                uint32_t b1 = __float_as_uint(Bs[buf][kk + 4 + tg][wn + nj * 8 + g]);
#pragma unroll
                for (int mi = 0; mi < 4; mi++) {
                    mma_tf32(acc[mi][nj], af[mi], b0, b1);
                }
            }
        }

        // ---- store prefetched tile into other buffer ----
        if (t < ntiles) {
            float* as = &As[buf ^ 1][aRow][aH];
            as[0] = to_tf32(ra0.x); as[1] = to_tf32(ra0.y); as[2] = to_tf32(ra0.z); as[3] = to_tf32(ra0.w);
            as[4] = to_tf32(ra1.x); as[5] = to_tf32(ra1.y); as[6] = to_tf32(ra1.z); as[7] = to_tf32(ra1.w);
            float* bs0 = &Bs[buf ^ 1][bRow][bC4];
            bs0[0] = to_tf32(rb0.x); bs0[1] = to_tf32(rb0.y); bs0[2] = to_tf32(rb0.z); bs0[3] = to_tf32(rb0.w);
            float* bs1 = &Bs[buf ^ 1][bRow + 8][bC4];
            bs1[0] = to_tf32(rb1.x); bs1[1] = to_tf32(rb1.y); bs1[2] = to_tf32(rb1.z); bs1[3] = to_tf32(rb1.w);
        }
        __syncthreads();
        buf ^= 1;
    }

    // ---- epilogue ----
#pragma unroll
    for (int nj = 0; nj < 4; nj++) {
        const int col = bn0 + wn + nj * 8 + tg * 2;
        if (col >= N) continue;
        float b0 = 0.f, b1 = 0.f;
        if (BIAS) { b0 = bias[col]; b1 = bias[col + 1]; }
#pragma unroll
        for (int mi = 0; mi < 4; mi++) {
            const int row0 = bm0 + wm + mi * 16 + g;
            float v0 = acc[mi][nj][0] + b0;
            float v1 = acc[mi][nj][1] + b1;
            float v2 = acc[mi][nj][2] + b0;
            float v3 = acc[mi][nj][3] + b1;
            if (RELU) {
                v0 = fmaxf(v0, 0.f); v1 = fmaxf(v1, 0.f);
                v2 = fmaxf(v2, 0.f); v3 = fmaxf(v3, 0.f);
            }
            if (row0 < M) {
                float2 o = make_float2(v0, v1);
                *reinterpret_cast<float2*>(C + (size_t)row0 * N + col) = o;
            }
            if (row0 + 8 < M) {
                float2 o = make_float2(v2, v3);
                *reinterpret_cast<float2*>(C + (size_t)(row0 + 8) * N + col) = o;
            }
        }
    }
}

// ---------------- edge scatter: agg[col] += src[row] * dis[row]*dis[col] ----------------
__global__ void scatter_kernel(const int* __restrict__ ei, int E,
                               const float* __restrict__ dis,
                               const float* __restrict__ src,
                               float* __restrict__ agg) {
    int warp = (blockIdx.x * blockDim.x + threadIdx.x) >> 5;
    int lane = threadIdx.x & 31;
    if (warp >= E) return;
    int r = ei[warp];
    int c = ei[E + warp];
    float nrm = dis[r] * dis[c];
    if (nrm == 0.f) return;
    float4 v = *reinterpret_cast<const float4*>(src + (size_t)r * 128 + lane * 4);
    float x = v.x * nrm, y = v.y * nrm, z = v.z * nrm, w = v.w * nrm;
    float* dst = agg + (size_t)c * 128 + lane * 4;
    asm volatile("red.global.add.v4.f32 [%0], {%1,%2,%3,%4};"
                 :: "l"(dst), "f"(x), "f"(y), "f"(z), "f"(w) : "memory");
}

// ---------------- assemble R1 (+bias) into r1 and final[:,0:512] ----------------
__global__ void build_r1_kernel(const float* __restrict__ agg_a, const float* __restrict__ agg_b,
                                const float* __restrict__ b_c1, const float* __restrict__ h,
                                float* __restrict__ r1, float* __restrict__ fin, int n) {
    size_t total = (size_t)n * 128;
    size_t stride = (size_t)gridDim.x * blockDim.x;
    for (size_t idx = (size_t)blockIdx.x * blockDim.x + threadIdx.x; idx < total; idx += stride) {
        size_t i = idx >> 7;
        int j = (int)(idx & 127);
        float va = agg_a[idx] + b_c1[j];
        float vb = agg_b[idx] + b_c1[j];
        r1[i * 256 + j]        = va;
        r1[i * 256 + 128 + j]  = vb;
        fin[i * DFIN + 256 + j] = va;
        fin[i * DFIN + 384 + j] = vb;
    }
    size_t total2 = (size_t)n * 256;
    for (size_t idx = (size_t)blockIdx.x * blockDim.x + threadIdx.x; idx < total2; idx += stride) {
        size_t i = idx >> 8;
        int j = (int)(idx & 255);
        fin[i * DFIN + j] = h[idx];
    }
}

// ---------------- assemble R2 (+bias) into final[:,512:768] ----------------
__global__ void build_r2_kernel(const float* __restrict__ agg_a, const float* __restrict__ agg_b,
                                const float* __restrict__ b_c2, float* __restrict__ fin, int n) {
    size_t total = (size_t)n * 128;
    size_t stride = (size_t)gridDim.x * blockDim.x;
    for (size_t idx = (size_t)blockIdx.x * blockDim.x + threadIdx.x; idx < total; idx += stride) {
        size_t i = idx >> 7;
        int j = (int)(idx & 127);
        fin[i * DFIN + 512 + j] = agg_a[idx] + b_c2[j];
        fin[i * DFIN + 640 + j] = agg_b[idx] + b_c2[j];
    }
}

// ---------------- log_softmax over 40 logits, one warp per row ----------------
__global__ void logsoftmax_kernel(const float* __restrict__ logits, float* __restrict__ out, int M) {
    int warp = (blockIdx.x * blockDim.x + threadIdx.x) >> 5;
    int lane = threadIdx.x & 31;
    if (warp >= M) return;
    const float* L = logits + (size_t)warp * NCLS;
    float v0 = L[lane];
    float v1 = (lane < NCLS - 32) ? L[32 + lane] : -INFINITY;
    float m = fmaxf(v0, v1);
#pragma unroll
    for (int o = 16; o > 0; o >>= 1) m = fmaxf(m, __shfl_xor_sync(0xffffffffu, m, o));
    float s = expf(v0 - m) + ((lane < NCLS - 32) ? expf(v1 - m) : 0.f);
#pragma unroll
    for (int o = 16; o > 0; o >>= 1) s += __shfl_xor_sync(0xffffffffu, s, o);
    float ls = logf(s);
    float* O = out + (size_t)warp * NCLS;
    O[lane] = v0 - m - ls;
    if (lane < NCLS - 32) O[32 + lane] = v1 - m - ls;
}

// ---------------- host launcher ----------------
extern "C" void kernel_launch(void* const* d_in, const int* in_sizes, int n_in,
                              void* d_out, int out_size) {
    const float* x       = (const float*)d_in[0];
    const int*   ei1     = (const int*)  d_in[1];
    const int*   ei2     = (const int*)  d_in[2];
    const float* W_lin1  = (const float*)d_in[3];
    const float* b_lin1  = (const float*)d_in[4];
    const float* W_c1    = (const float*)d_in[5];
    const float* b_c1    = (const float*)d_in[6];
    const float* W_c2    = (const float*)d_in[7];
    const float* b_c2    = (const float*)d_in[8];
    const float* W_lin2  = (const float*)d_in[9];
    const float* b_lin2  = (const float*)d_in[10];
    float* out = (float*)d_out;

    const int E1 = in_sizes[1] / 2;
    const int E2 = in_sizes[2] / 2;
    const int n  = NNODES;

    float *p_h, *p_hw, *p_agg_a, *p_agg_b, *p_r1, *p_final, *p_logits;
    float *p_deg1, *p_deg2, *p_dis1, *p_dis2;
    cudaGetSymbolAddress((void**)&p_h,      g_h);
    cudaGetSymbolAddress((void**)&p_hw,     g_hw);
    cudaGetSymbolAddress((void**)&p_agg_a,  g_agg_a);
    cudaGetSymbolAddress((void**)&p_agg_b,  g_agg_b);
    cudaGetSymbolAddress((void**)&p_r1,     g_r1);
    cudaGetSymbolAddress((void**)&p_final,  g_final);
    cudaGetSymbolAddress((void**)&p_logits, g_logits);
    cudaGetSymbolAddress((void**)&p_deg1,   g_deg1);
    cudaGetSymbolAddress((void**)&p_deg2,   g_deg2);
    cudaGetSymbolAddress((void**)&p_dis1,   g_dis1);
    cudaGetSymbolAddress((void**)&p_dis2,   g_dis2);

    // --- zero degree + aggregate buffers ---
    zero_kernel<<<512, 256>>>(p_deg1, NNODES / 4);
    zero_kernel<<<512, 256>>>(p_deg2, NNODES / 4);
    zero_kernel<<<2048, 256>>>(p_agg_a, (size_t)n * 128 / 4);
    zero_kernel<<<2048, 256>>>(p_agg_b, (size_t)n * 128 / 4);

    // --- degrees & normalization ---
    deg_kernel<<<(E1 + 255) / 256, 256>>>(ei1, E1, p_deg1);
    deg_kernel<<<(E2 + 255) / 256, 256>>>(ei2, E2, p_deg2);
    dis_kernel<<<(n + 255) / 256, 256>>>(p_deg1, p_dis1, n);
    dis_kernel<<<(n + 255) / 256, 256>>>(p_deg2, p_dis2, n);

    const int gy = (n + 127) / 128;  // 391

    // --- h = relu(x @ W_lin1 + b_lin1)  [50000,512]x[512,256] ---
    mma_gemm_kernel<true, true><<<dim3(H0 / 128, gy), 256>>>(x, W_lin1, b_lin1, p_h, n, H0, F_IN);

    // --- hw = h @ W_c1 (shared by both edge sets)  [50000,256]x[256,128] ---
    mma_gemm_kernel<false, false><<<dim3(1, gy), 256>>>(p_h, W_c1, nullptr, p_hw, n, H1, H0);

    // --- layer-1 scatters ---
    scatter_kernel<<<(E1 + 7) / 8, 256>>>(ei1, E1, p_dis1, p_hw, p_agg_a);
    scatter_kernel<<<(E2 + 7) / 8, 256>>>(ei2, E2, p_dis2, p_hw, p_agg_b);

    // --- R1 = [agg_a+b, agg_b+b]; also fill final[:,0:512] ---
    build_r1_kernel<<<2048, 256>>>(p_agg_a, p_agg_b, b_c1, p_h, p_r1, p_final, n);

    // --- re-zero aggregates for layer 2 ---
    zero_kernel<<<2048, 256>>>(p_agg_a, (size_t)n * 128 / 4);
    zero_kernel<<<2048, 256>>>(p_agg_b, (size_t)n * 128 / 4);

    // --- hw = R1 @ W_c2  [50000,256]x[256,128] ---
    mma_gemm_kernel<false, false><<<dim3(1, gy), 256>>>(p_r1, W_c2, nullptr, p_hw, n, H2, 2 * H1);

    // --- layer-2 scatters ---
    scatter_kernel<<<(E1 + 7) / 8, 256>>>(ei1, E1, p_dis1, p_hw, p_agg_a);
    scatter_kernel<<<(E2 + 7) / 8, 256>>>(ei2, E2, p_dis2, p_hw, p_agg_b);

    // --- final[:,512:768] = R2 + b_c2 ---
    build_r2_kernel<<<2048, 256>>>(p_agg_a, p_agg_b, b_c2, p_final, n);

    // --- logits = final @ W_lin2 + b_lin2  [50000,768]x[768,40] ---
    mma_gemm_kernel<false, true><<<dim3(1, gy), 256>>>(p_final, W_lin2, b_lin2, p_logits, n, NCLS, DFIN);

    // --- log_softmax -> out ---
    logsoftmax_kernel<<<(n + 7) / 8, 256>>>(p_logits, out, n);
}

// round 3
// speedup vs baseline: 2.0448x; 1.4704x over previous
#include <cuda_runtime.h>
#include <cuda_bf16.h>
#include <cstdint>
#include <math.h>

// ---------------- problem constants ----------------
#define NNODES 50000
#define F_IN   512
#define H0     256
#define H1     128
#define H2     128
#define NCLS   40
#define DFIN   768
#define E1MAX  800000
#define E2MAX  1600000

// ---------------- static scratch ----------------
__device__ float g_hw[(size_t)NNODES * H1];
__device__ float g_final[(size_t)NNODES * DFIN];
__device__ float g_logits[(size_t)NNODES * NCLS];
__device__ float g_dis1[NNODES];
__device__ float g_dis2[NNODES];
__device__ int   g_cnt1[NNODES];
__device__ int   g_cnt2[NNODES];
__device__ int   g_rowptr1[NNODES + 1];
__device__ int   g_rowptr2[NNODES + 1];
__device__ int   g_cursor1[NNODES];
__device__ int   g_cursor2[NNODES];
__device__ int   g_adj1[E1MAX];
__device__ int   g_adj2[E2MAX];

// ---------------- CSR build ----------------
__global__ void zero_int_kernel(int* __restrict__ p, int n) {
    int i = blockIdx.x * blockDim.x + threadIdx.x;
    if (i < n) p[i] = 0;
}

__global__ void hist_kernel(const int* __restrict__ ei, int E, int* __restrict__ cnt) {
    int e = blockIdx.x * blockDim.x + threadIdx.x;
    if (e < E) atomicAdd(&cnt[ei[E + e]], 1);
}

// single-block exclusive scan over cnt[n]; also fills cursor copy and dis=rsqrt(deg)
__global__ __launch_bounds__(1024)
void scan_kernel(const int* __restrict__ cnt, int* __restrict__ rowptr,
                 int* __restrict__ cursor, float* __restrict__ dis, int n) {
    __shared__ int part[1024];
    const int t = threadIdx.x;
    const int chunk = (n + 1023) / 1024;
    const int s0 = min(t * chunk, n);
    const int s1 = min(s0 + chunk, n);
    int sum = 0;
    for (int i = s0; i < s1; i++) sum += cnt[i];
    part[t] = sum;
    __syncthreads();
    for (int off = 1; off < 1024; off <<= 1) {
        int v = part[t];
        int o = (t >= off) ? part[t - off] : 0;
        __syncthreads();
        part[t] = v + o;
        __syncthreads();
    }
    int run = (t == 0) ? 0 : part[t - 1];
    for (int i = s0; i < s1; i++) {
        rowptr[i] = run;
        cursor[i] = run;
        int c = cnt[i];
        dis[i] = (c > 0) ? rsqrtf((float)c) : 0.f;
        run += c;
    }
    if (t == 1023) rowptr[n] = part[1023];
}

__global__ void fill_kernel(const int* __restrict__ ei, int E,
                            int* __restrict__ cursor, int* __restrict__ adj) {
    int e = blockIdx.x * blockDim.x + threadIdx.x;
    if (e < E) {
        int r = ei[e];
        int c = ei[E + e];
        int slot = atomicAdd(&cursor[c], 1);
        adj[slot] = r;
    }
}

// ---------------- TF32 helpers ----------------
__device__ __forceinline__ float to_tf32(float x) {
    uint32_t u;
    asm("cvt.rna.tf32.f32 %0, %1;" : "=r"(u) : "f"(x));
    return __uint_as_float(u);
}

__device__ __forceinline__ void mma_tf32(float* c, const uint32_t* a, uint32_t b0, uint32_t b1) {
    asm volatile(
        "mma.sync.aligned.m16n8k8.row.col.f32.tf32.tf32.f32 "
        "{%0,%1,%2,%3}, {%4,%5,%6,%7}, {%8,%9}, {%0,%1,%2,%3};"
        : "+f"(c[0]), "+f"(c[1]), "+f"(c[2]), "+f"(c[3])
        : "r"(a[0]), "r"(a[1]), "r"(a[2]), "r"(a[3]), "r"(b0), "r"(b1));
}

// ---------------- TF32 tensor-core GEMM with lda/ldc ----------------
// C[M,N] (ldc) = op(A[M,K] (lda) @ B[K,N] + bias); block 128x128, BK=16, 8 warps.
#define AS_STRIDE 20
#define BS_STRIDE 132
template <bool RELU, bool BIAS>
__global__ __launch_bounds__(256)
void mma_gemm_kernel(const float* __restrict__ A, int lda,
                     const float* __restrict__ B,
                     const float* __restrict__ bias,
                     float* __restrict__ C, int ldc,
                     int M, int N, int K) {
    __shared__ float As[2][128][AS_STRIDE];
    __shared__ float Bs[2][16][BS_STRIDE];

    const int tid  = threadIdx.x;
    const int lane = tid & 31;
    const int warp = tid >> 5;
    const int bm0 = blockIdx.y * 128;
    const int bn0 = blockIdx.x * 128;
    const int wm = (warp & 1) * 64;
    const int wn = (warp >> 1) * 32;
    const int g  = lane >> 2;
    const int tg = lane & 3;

    float acc[4][4][4];
#pragma unroll
    for (int i = 0; i < 4; i++)
#pragma unroll
        for (int j = 0; j < 4; j++)
#pragma unroll
            for (int q = 0; q < 4; q++) acc[i][j][q] = 0.f;

    const int aRow = tid >> 1;
    const int aH   = (tid & 1) * 8;
    const bool aValid = (bm0 + aRow) < M;
    const float* Aptr = A + (size_t)(bm0 + aRow) * lda + aH;

    const int bRow = tid >> 5;
    const int bC4  = (tid & 31) * 4;
    const bool bValid = (bn0 + bC4) < N;
    const float* Bptr = B + (size_t)bRow * N + bn0 + bC4;

    const int ntiles = K / 16;
    const float4 zero4 = make_float4(0.f, 0.f, 0.f, 0.f);

    float4 ra0 = zero4, ra1 = zero4, rb0 = zero4, rb1 = zero4;
    if (aValid) {
        ra0 = *reinterpret_cast<const float4*>(Aptr);
        ra1 = *reinterpret_cast<const float4*>(Aptr + 4);
    }
    if (bValid) {
        rb0 = *reinterpret_cast<const float4*>(Bptr);
        rb1 = *reinterpret_cast<const float4*>(Bptr + (size_t)8 * N);
    }
    {
        float* as = &As[0][aRow][aH];
        as[0] = to_tf32(ra0.x); as[1] = to_tf32(ra0.y); as[2] = to_tf32(ra0.z); as[3] = to_tf32(ra0.w);
        as[4] = to_tf32(ra1.x); as[5] = to_tf32(ra1.y); as[6] = to_tf32(ra1.z); as[7] = to_tf32(ra1.w);
        float* bs0 = &Bs[0][bRow][bC4];
        bs0[0] = to_tf32(rb0.x); bs0[1] = to_tf32(rb0.y); bs0[2] = to_tf32(rb0.z); bs0[3] = to_tf32(rb0.w);
        float* bs1 = &Bs[0][bRow + 8][bC4];
        bs1[0] = to_tf32(rb1.x); bs1[1] = to_tf32(rb1.y); bs1[2] = to_tf32(rb1.z); bs1[3] = to_tf32(rb1.w);
    }
    __syncthreads();

    const int lm_row = wm + (lane & 7) + ((lane >> 3) & 1) * 8;
    const int lm_kq  = (lane >> 4) * 4;

    int buf = 0;
    for (int t = 1; t <= ntiles; t++) {
        if (t < ntiles) {
            const int k0 = t * 16;
            if (aValid) {
                ra0 = *reinterpret_cast<const float4*>(Aptr + k0);
                ra1 = *reinterpret_cast<const float4*>(Aptr + k0 + 4);
            }
            if (bValid) {
                rb0 = *reinterpret_cast<const float4*>(Bptr + (size_t)k0 * N);
                rb1 = *reinterpret_cast<const float4*>(Bptr + (size_t)(k0 + 8) * N);
            }
        }

#pragma unroll
        for (int kk = 0; kk < 16; kk += 8) {
            uint32_t af[4][4];
#pragma unroll
            for (int mi = 0; mi < 4; mi++) {
                uint32_t saddr = (uint32_t)__cvta_generic_to_shared(
                    &As[buf][lm_row + mi * 16][kk + lm_kq]);
                asm volatile("ldmatrix.sync.aligned.m8n8.x4.shared.b16 {%0,%1,%2,%3}, [%4];"
                             : "=r"(af[mi][0]), "=r"(af[mi][1]), "=r"(af[mi][2]), "=r"(af[mi][3])
                             : "r"(saddr));
            }
#pragma unroll
            for (int nj = 0; nj < 4; nj++) {
                uint32_t b0 = __float_as_uint(Bs[buf][kk + tg][wn + nj * 8 + g]);
                uint32_t b1 = __float_as_uint(Bs[buf][kk + 4 + tg][wn + nj * 8 + g]);
#pragma unroll
                for (int mi = 0; mi < 4; mi++) {
                    mma_tf32(acc[mi][nj], af[mi], b0, b1);
                }
            }
        }

        if (t < ntiles) {
            float* as = &As[buf ^ 1][aRow][aH];
            as[0] = to_tf32(ra0.x); as[1] = to_tf32(ra0.y); as[2] = to_tf32(ra0.z); as[3] = to_tf32(ra0.w);
            as[4] = to_tf32(ra1.x); as[5] = to_tf32(ra1.y); as[6] = to_tf32(ra1.z); as[7] = to_tf32(ra1.w);
            float* bs0 = &Bs[buf ^ 1][bRow][bC4];
            bs0[0] = to_tf32(rb0.x); bs0[1] = to_tf32(rb0.y); bs0[2] = to_tf32(rb0.z); bs0[3] = to_tf32(rb0.w);
            float* bs1 = &Bs[buf ^ 1][bRow + 8][bC4];
            bs1[0] = to_tf32(rb1.x); bs1[1] = to_tf32(rb1.y); bs1[2] = to_tf32(rb1.z); bs1[3] = to_tf32(rb1.w);
        }
        __syncthreads();
        buf ^= 1;
    }

#pragma unroll
    for (int nj = 0; nj < 4; nj++) {
        const int col = bn0 + wn + nj * 8 + tg * 2;
        if (col >= N) continue;
        float b0 = 0.f, b1 = 0.f;
        if (BIAS) { b0 = bias[col]; b1 = bias[col + 1]; }
#pragma unroll
        for (int mi = 0; mi < 4; mi++) {
            const int row0 = bm0 + wm + mi * 16 + g;
            float v0 = acc[mi][nj][0] + b0;
            float v1 = acc[mi][nj][1] + b1;
            float v2 = acc[mi][nj][2] + b0;
            float v3 = acc[mi][nj][3] + b1;
            if (RELU) {
                v0 = fmaxf(v0, 0.f); v1 = fmaxf(v1, 0.f);
                v2 = fmaxf(v2, 0.f); v3 = fmaxf(v3, 0.f);
            }
            if (row0 < M) {
                *reinterpret_cast<float2*>(C + (size_t)row0 * ldc + col) = make_float2(v0, v1);
            }
            if (row0 + 8 < M) {
                *reinterpret_cast<float2*>(C + (size_t)(row0 + 8) * ldc + col) = make_float2(v2, v3);
            }
        }
    }
}

// ---------------- CSR gather-aggregate: one warp per node ----------------
// out[node, 0:128] = (sum_{e in CSR[node]} src[adj[e]] * dis[adj[e]]) * dis[node] + bias
__global__ __launch_bounds__(256)
void gather_kernel(const int* __restrict__ rowptr, const int* __restrict__ adj,
                   const float* __restrict__ dis, const float* __restrict__ src,
                   const float* __restrict__ bias, float* __restrict__ outp,
                   int ldc, int n) {
    int node = (blockIdx.x * blockDim.x + threadIdx.x) >> 5;
    int lane = threadIdx.x & 31;
    if (node >= n) return;
    int s = rowptr[node];
    int e = rowptr[node + 1];
    float ax = 0.f, ay = 0.f, az = 0.f, aw = 0.f;
#pragma unroll 4
    for (int i = s; i < e; i++) {
        int r = __ldg(&adj[i]);
        float nr = __ldg(&dis[r]);
        float4 v = *reinterpret_cast<const float4*>(src + (size_t)r * 128 + lane * 4);
        ax = fmaf(v.x, nr, ax);
        ay = fmaf(v.y, nr, ay);
        az = fmaf(v.z, nr, az);
        aw = fmaf(v.w, nr, aw);
    }
    float dc = dis[node];
    float4 b = *reinterpret_cast<const float4*>(bias + lane * 4);
    float4 o;
    o.x = fmaf(ax, dc, b.x);
    o.y = fmaf(ay, dc, b.y);
    o.z = fmaf(az, dc, b.z);
    o.w = fmaf(aw, dc, b.w);
    *reinterpret_cast<float4*>(outp + (size_t)node * ldc + lane * 4) = o;
}

// ---------------- log_softmax over 40 logits, one warp per row ----------------
__global__ void logsoftmax_kernel(const float* __restrict__ logits, float* __restrict__ out, int M) {
    int warp = (blockIdx.x * blockDim.x + threadIdx.x) >> 5;
    int lane = threadIdx.x & 31;
    if (warp >= M) return;
    const float* L = logits + (size_t)warp * NCLS;
    float v0 = L[lane];
    float v1 = (lane < NCLS - 32) ? L[32 + lane] : -INFINITY;
    float m = fmaxf(v0, v1);
#pragma unroll
    for (int o = 16; o > 0; o >>= 1) m = fmaxf(m, __shfl_xor_sync(0xffffffffu, m, o));
    float s = expf(v0 - m) + ((lane < NCLS - 32) ? expf(v1 - m) : 0.f);
#pragma unroll
    for (int o = 16; o > 0; o >>= 1) s += __shfl_xor_sync(0xffffffffu, s, o);
    float ls = logf(s);
    float* O = out + (size_t)warp * NCLS;
    O[lane] = v0 - m - ls;
    if (lane < NCLS - 32) O[32 + lane] = v1 - m - ls;
}

// ---------------- host launcher ----------------
extern "C" void kernel_launch(void* const* d_in, const int* in_sizes, int n_in,
                              void* d_out, int out_size) {
    const float* x       = (const float*)d_in[0];
    const int*   ei1     = (const int*)  d_in[1];
    const int*   ei2     = (const int*)  d_in[2];
    const float* W_lin1  = (const float*)d_in[3];
    const float* b_lin1  = (const float*)d_in[4];
    const float* W_c1    = (const float*)d_in[5];
    const float* b_c1    = (const float*)d_in[6];
    const float* W_c2    = (const float*)d_in[7];
    const float* b_c2    = (const float*)d_in[8];
    const float* W_lin2  = (const float*)d_in[9];
    const float* b_lin2  = (const float*)d_in[10];
    float* out = (float*)d_out;

    const int E1 = in_sizes[1] / 2;
    const int E2 = in_sizes[2] / 2;
    const int n  = NNODES;

    float *p_hw, *p_final, *p_logits, *p_dis1, *p_dis2;
    int *p_cnt1, *p_cnt2, *p_rp1, *p_rp2, *p_cur1, *p_cur2, *p_adj1, *p_adj2;
    cudaGetSymbolAddress((void**)&p_hw,     g_hw);
    cudaGetSymbolAddress((void**)&p_final,  g_final);
    cudaGetSymbolAddress((void**)&p_logits, g_logits);
    cudaGetSymbolAddress((void**)&p_dis1,   g_dis1);
    cudaGetSymbolAddress((void**)&p_dis2,   g_dis2);
    cudaGetSymbolAddress((void**)&p_cnt1,   g_cnt1);
    cudaGetSymbolAddress((void**)&p_cnt2,   g_cnt2);
    cudaGetSymbolAddress((void**)&p_rp1,    g_rowptr1);
    cudaGetSymbolAddress((void**)&p_rp2,    g_rowptr2);
    cudaGetSymbolAddress((void**)&p_cur1,   g_cursor1);
    cudaGetSymbolAddress((void**)&p_cur2,   g_cursor2);
    cudaGetSymbolAddress((void**)&p_adj1,   g_adj1);
    cudaGetSymbolAddress((void**)&p_adj2,   g_adj2);

    // ---- CSR build for both edge sets ----
    zero_int_kernel<<<(n + 255) / 256, 256>>>(p_cnt1, n);
    zero_int_kernel<<<(n + 255) / 256, 256>>>(p_cnt2, n);
    hist_kernel<<<(E1 + 255) / 256, 256>>>(ei1, E1, p_cnt1);
    hist_kernel<<<(E2 + 255) / 256, 256>>>(ei2, E2, p_cnt2);
    scan_kernel<<<1, 1024>>>(p_cnt1, p_rp1, p_cur1, p_dis1, n);
    scan_kernel<<<1, 1024>>>(p_cnt2, p_rp2, p_cur2, p_dis2, n);
    fill_kernel<<<(E1 + 255) / 256, 256>>>(ei1, E1, p_cur1, p_adj1);
    fill_kernel<<<(E2 + 255) / 256, 256>>>(ei2, E2, p_cur2, p_adj2);

    const int gy = (n + 127) / 128;  // 391
    const int gather_grid = (n * 32 + 255) / 256;

    // ---- h = relu(x @ W_lin1 + b_lin1) -> final[:, 0:256] ----
    mma_gemm_kernel<true, true><<<dim3(H0 / 128, gy), 256>>>(
        x, F_IN, W_lin1, b_lin1, p_final, DFIN, n, H0, F_IN);

    // ---- hw = h @ W_c1 (shared by both edge sets) ----
    mma_gemm_kernel<false, false><<<dim3(1, gy), 256>>>(
        p_final, DFIN, W_c1, nullptr, p_hw, H1, n, H1, H0);

    // ---- layer-1 gathers -> final[:, 256:384], final[:, 384:512] (bias fused) ----
    gather_kernel<<<gather_grid, 256>>>(p_rp1, p_adj1, p_dis1, p_hw, b_c1, p_final + 256, DFIN, n);
    gather_kernel<<<gather_grid, 256>>>(p_rp2, p_adj2, p_dis2, p_hw, b_c1, p_final + 384, DFIN, n);

    // ---- hw = R1 @ W_c2  (R1 = final[:, 256:512]) ----
    mma_gemm_kernel<false, false><<<dim3(1, gy), 256>>>(
        p_final + 256, DFIN, W_c2, nullptr, p_hw, H2, n, H2, 2 * H1);

    // ---- layer-2 gathers -> final[:, 512:640], final[:, 640:768] ----
    gather_kernel<<<gather_grid, 256>>>(p_rp1, p_adj1, p_dis1, p_hw, b_c2, p_final + 512, DFIN, n);
    gather_kernel<<<gather_grid, 256>>>(p_rp2, p_adj2, p_dis2, p_hw, b_c2, p_final + 640, DFIN, n);

    // ---- logits = final @ W_lin2 + b_lin2 ----
    mma_gemm_kernel<false, true><<<dim3(1, gy), 256>>>(
        p_final, DFIN, W_lin2, b_lin2, p_logits, NCLS, n, NCLS, DFIN);

    // ---- log_softmax -> out ----
    logsoftmax_kernel<<<(n + 7) / 8, 256>>>(p_logits, out, n);
}

// round 4
// speedup vs baseline: 2.6448x; 1.2934x over previous
#include <cuda_runtime.h>
#include <cuda_bf16.h>
#include <cstdint>
#include <math.h>

// ---------------- problem constants ----------------
#define NNODES 50000
#define F_IN   512
#define H0     256
#define H1     128
#define H2     128
#define NCLS   40
#define DFIN   768
#define E1MAX  800000
#define E2MAX  1600000

// ---------------- static scratch ----------------
__device__ __nv_bfloat16 g_hwh[(size_t)NNODES * H1];  // bf16 message buffer
__device__ float g_final[(size_t)NNODES * DFIN];
__device__ float g_logits[(size_t)NNODES * NCLS];
__device__ float g_dis1[NNODES];
__device__ float g_dis2[NNODES];
__device__ int   g_cnt1[NNODES];
__device__ int   g_cnt2[NNODES];
__device__ int   g_rowptr1[NNODES + 1];
__device__ int   g_rowptr2[NNODES + 1];
__device__ int   g_cursor1[NNODES];
__device__ int   g_cursor2[NNODES];
__device__ int   g_adj1[E1MAX];
__device__ int   g_adj2[E2MAX];

// ---------------- CSR build (merged kernels) ----------------
__global__ void zero2_kernel(int* __restrict__ p1, int* __restrict__ p2, int n) {
    int i = blockIdx.x * blockDim.x + threadIdx.x;
    if (i < n) { p1[i] = 0; p2[i] = 0; }
}

__global__ void hist2_kernel(const int* __restrict__ ei1, int E1, int* __restrict__ cnt1,
                             const int* __restrict__ ei2, int E2, int* __restrict__ cnt2) {
    int i = blockIdx.x * blockDim.x + threadIdx.x;
    if (i < E1) {
        atomicAdd(&cnt1[ei1[E1 + i]], 1);
    } else if (i < E1 + E2) {
        int j = i - E1;
        atomicAdd(&cnt2[ei2[E2 + j]], 1);
    }
}

// 2 blocks: block b handles edge set b. Exclusive scan + cursor + dis=rsqrt(deg).
__global__ __launch_bounds__(1024)
void scan2_kernel(int* __restrict__ cnt1, int* __restrict__ rp1, int* __restrict__ cur1, float* __restrict__ dis1,
                  int* __restrict__ cnt2, int* __restrict__ rp2, int* __restrict__ cur2, float* __restrict__ dis2,
                  int n) {
    const int* cnt = (blockIdx.x == 0) ? cnt1 : cnt2;
    int* rowptr    = (blockIdx.x == 0) ? rp1  : rp2;
    int* cursor    = (blockIdx.x == 0) ? cur1 : cur2;
    float* dis     = (blockIdx.x == 0) ? dis1 : dis2;
    __shared__ int part[1024];
    const int t = threadIdx.x;
    const int chunk = (n + 1023) / 1024;
    const int s0 = min(t * chunk, n);
    const int s1 = min(s0 + chunk, n);
    int sum = 0;
    for (int i = s0; i < s1; i++) sum += cnt[i];
    part[t] = sum;
    __syncthreads();
    for (int off = 1; off < 1024; off <<= 1) {
        int v = part[t];
        int o = (t >= off) ? part[t - off] : 0;
        __syncthreads();
        part[t] = v + o;
        __syncthreads();
    }
    int run = (t == 0) ? 0 : part[t - 1];
    for (int i = s0; i < s1; i++) {
        rowptr[i] = run;
        cursor[i] = run;
        int c = cnt[i];
        dis[i] = (c > 0) ? rsqrtf((float)c) : 0.f;
        run += c;
    }
    if (t == 1023) rowptr[n] = part[1023];
}

__global__ void fill2_kernel(const int* __restrict__ ei1, int E1, int* __restrict__ cur1, int* __restrict__ adj1,
                             const int* __restrict__ ei2, int E2, int* __restrict__ cur2, int* __restrict__ adj2) {
    int i = blockIdx.x * blockDim.x + threadIdx.x;
    if (i < E1) {
        int slot = atomicAdd(&cur1[ei1[E1 + i]], 1);
        adj1[slot] = ei1[i];
    } else if (i < E1 + E2) {
        int j = i - E1;
        int slot = atomicAdd(&cur2[ei2[E2 + j]], 1);
        adj2[slot] = ei2[j];
    }
}

// ---------------- TF32 helpers ----------------
__device__ __forceinline__ float to_tf32(float x) {
    uint32_t u;
    asm("cvt.rna.tf32.f32 %0, %1;" : "=r"(u) : "f"(x));
    return __uint_as_float(u);
}

__device__ __forceinline__ void mma_tf32(float* c, const uint32_t* a, uint32_t b0, uint32_t b1) {
    asm volatile(
        "mma.sync.aligned.m16n8k8.row.col.f32.tf32.tf32.f32 "
        "{%0,%1,%2,%3}, {%4,%5,%6,%7}, {%8,%9}, {%0,%1,%2,%3};"
        : "+f"(c[0]), "+f"(c[1]), "+f"(c[2]), "+f"(c[3])
        : "r"(a[0]), "r"(a[1]), "r"(a[2]), "r"(a[3]), "r"(b0), "r"(b1));
}

// ---------------- TF32 tensor-core GEMM, templated tile width ----------------
// BM=128, BN in {128, 64}; 8 warps. BN=128: warp tile 64x32; BN=64: warp tile 32x32.
// OUTBF: write C as bf16 (ldc in elements).
template <int BN, bool RELU, bool BIAS, bool OUTBF>
__global__ __launch_bounds__(256)
void mma_gemm_kernel(const float* __restrict__ A, int lda,
                     const float* __restrict__ B,
                     const float* __restrict__ bias,
                     void* __restrict__ Cv, int ldc,
                     int M, int N, int K) {
    constexpr int MI = (BN == 128) ? 4 : 2;
    __shared__ float As[2][128][20];
    __shared__ float Bs[2][16][BN + 4];

    const int tid  = threadIdx.x;
    const int lane = tid & 31;
    const int warp = tid >> 5;
    const int bm0 = blockIdx.y * 128;
    const int bn0 = blockIdx.x * BN;
    const int wm = (BN == 128) ? (warp & 1) * 64 : (warp & 3) * 32;
    const int wn = (BN == 128) ? (warp >> 1) * 32 : (warp >> 2) * 32;
    const int g  = lane >> 2;
    const int tg = lane & 3;

    float acc[MI][4][4];
#pragma unroll
    for (int i = 0; i < MI; i++)
#pragma unroll
        for (int j = 0; j < 4; j++)
#pragma unroll
            for (int q = 0; q < 4; q++) acc[i][j][q] = 0.f;

    // A tile: 128 rows x 16 k, each thread loads 8 consecutive floats
    const int aRow = tid >> 1;
    const int aH   = (tid & 1) * 8;
    const bool aValid = (bm0 + aRow) < M;
    const float* Aptr = A + (size_t)(bm0 + aRow) * lda + aH;

    // B tile: 16 rows x BN cols.
    // BN=128: 2 float4 per thread (rows tid/32 and +8). BN=64: 1 float4 (row tid/16).
    const int bRow = (BN == 128) ? (tid >> 5) : (tid >> 4);
    const int bC4  = (BN == 128) ? (tid & 31) * 4 : (tid & 15) * 4;
    const bool bValid = (bn0 + bC4) < N;
    const float* Bptr = B + (size_t)bRow * N + bn0 + bC4;

    const int ntiles = K / 16;
    const float4 zero4 = make_float4(0.f, 0.f, 0.f, 0.f);

    float4 ra0 = zero4, ra1 = zero4, rb0 = zero4, rb1 = zero4;
    if (aValid) {
        ra0 = *reinterpret_cast<const float4*>(Aptr);
        ra1 = *reinterpret_cast<const float4*>(Aptr + 4);
    }
    if (bValid) {
        rb0 = *reinterpret_cast<const float4*>(Bptr);
        if (BN == 128) rb1 = *reinterpret_cast<const float4*>(Bptr + (size_t)8 * N);
    }
    {
        float* as = &As[0][aRow][aH];
        as[0] = to_tf32(ra0.x); as[1] = to_tf32(ra0.y); as[2] = to_tf32(ra0.z); as[3] = to_tf32(ra0.w);
        as[4] = to_tf32(ra1.x); as[5] = to_tf32(ra1.y); as[6] = to_tf32(ra1.z); as[7] = to_tf32(ra1.w);
        float* bs0 = &Bs[0][bRow][bC4];
        bs0[0] = to_tf32(rb0.x); bs0[1] = to_tf32(rb0.y); bs0[2] = to_tf32(rb0.z); bs0[3] = to_tf32(rb0.w);
        if (BN == 128) {
            float* bs1 = &Bs[0][bRow + 8][bC4];
            bs1[0] = to_tf32(rb1.x); bs1[1] = to_tf32(rb1.y); bs1[2] = to_tf32(rb1.z); bs1[3] = to_tf32(rb1.w);
        }
    }
    __syncthreads();

    const int lm_row = wm + (lane & 7) + ((lane >> 3) & 1) * 8;
    const int lm_kq  = (lane >> 4) * 4;

    int buf = 0;
    for (int t = 1; t <= ntiles; t++) {
        if (t < ntiles) {
            const int k0 = t * 16;
            if (aValid) {
                ra0 = *reinterpret_cast<const float4*>(Aptr + k0);
                ra1 = *reinterpret_cast<const float4*>(Aptr + k0 + 4);
            }
            if (bValid) {
                rb0 = *reinterpret_cast<const float4*>(Bptr + (size_t)k0 * N);
                if (BN == 128) rb1 = *reinterpret_cast<const float4*>(Bptr + (size_t)(k0 + 8) * N);
            }
        }

#pragma unroll
        for (int kk = 0; kk < 16; kk += 8) {
            uint32_t af[MI][4];
#pragma unroll
            for (int mi = 0; mi < MI; mi++) {
                uint32_t saddr = (uint32_t)__cvta_generic_to_shared(
                    &As[buf][lm_row + mi * 16][kk + lm_kq]);
                asm volatile("ldmatrix.sync.aligned.m8n8.x4.shared.b16 {%0,%1,%2,%3}, [%4];"
                             : "=r"(af[mi][0]), "=r"(af[mi][1]), "=r"(af[mi][2]), "=r"(af[mi][3])
                             : "r"(saddr));
            }
#pragma unroll
            for (int nj = 0; nj < 4; nj++) {
                uint32_t b0 = __float_as_uint(Bs[buf][kk + tg][wn + nj * 8 + g]);
                uint32_t b1 = __float_as_uint(Bs[buf][kk + 4 + tg][wn + nj * 8 + g]);
#pragma unroll
                for (int mi = 0; mi < MI; mi++) {
                    mma_tf32(acc[mi][nj], af[mi], b0, b1);
                }
            }
        }

        if (t < ntiles) {
            float* as = &As[buf ^ 1][aRow][aH];
            as[0] = to_tf32(ra0.x); as[1] = to_tf32(ra0.y); as[2] = to_tf32(ra0.z); as[3] = to_tf32(ra0.w);
            as[4] = to_tf32(ra1.x); as[5] = to_tf32(ra1.y); as[6] = to_tf32(ra1.z); as[7] = to_tf32(ra1.w);
            float* bs0 = &Bs[buf ^ 1][bRow][bC4];
            bs0[0] = to_tf32(rb0.x); bs0[1] = to_tf32(rb0.y); bs0[2] = to_tf32(rb0.z); bs0[3] = to_tf32(rb0.w);
            if (BN == 128) {
                float* bs1 = &Bs[buf ^ 1][bRow + 8][bC4];
                bs1[0] = to_tf32(rb1.x); bs1[1] = to_tf32(rb1.y); bs1[2] = to_tf32(rb1.z); bs1[3] = to_tf32(rb1.w);
            }
        }
        __syncthreads();
        buf ^= 1;
    }

#pragma unroll
    for (int nj = 0; nj < 4; nj++) {
        const int col = bn0 + wn + nj * 8 + tg * 2;
        if (col >= N) continue;
        float b0 = 0.f, b1 = 0.f;
        if (BIAS) { b0 = bias[col]; b1 = bias[col + 1]; }
#pragma unroll
        for (int mi = 0; mi < MI; mi++) {
            const int row0 = bm0 + wm + mi * 16 + g;
            float v0 = acc[mi][nj][0] + b0;
            float v1 = acc[mi][nj][1] + b1;
            float v2 = acc[mi][nj][2] + b0;
            float v3 = acc[mi][nj][3] + b1;
            if (RELU) {
                v0 = fmaxf(v0, 0.f); v1 = fmaxf(v1, 0.f);
                v2 = fmaxf(v2, 0.f); v3 = fmaxf(v3, 0.f);
            }
            if (OUTBF) {
                __nv_bfloat16* C = (__nv_bfloat16*)Cv;
                if (row0 < M) {
                    *reinterpret_cast<__nv_bfloat162*>(C + (size_t)row0 * ldc + col) =
                        __floats2bfloat162_rn(v0, v1);
                }
                if (row0 + 8 < M) {
                    *reinterpret_cast<__nv_bfloat162*>(C + (size_t)(row0 + 8) * ldc + col) =
                        __floats2bfloat162_rn(v2, v3);
                }
            } else {
                float* C = (float*)Cv;
                if (row0 < M) {
                    *reinterpret_cast<float2*>(C + (size_t)row0 * ldc + col) = make_float2(v0, v1);
                }
                if (row0 + 8 < M) {
                    *reinterpret_cast<float2*>(C + (size_t)(row0 + 8) * ldc + col) = make_float2(v2, v3);
                }
            }
        }
    }
}

// ---------------- CSR gather-aggregate (bf16 source): one warp per node ----------------
__device__ __forceinline__ float4 bf4_to_f4(uint2 u) {
    __nv_bfloat162 p0 = *reinterpret_cast<__nv_bfloat162*>(&u.x);
    __nv_bfloat162 p1 = *reinterpret_cast<__nv_bfloat162*>(&u.y);
    float2 f0 = __bfloat1622float2(p0);
    float2 f1 = __bfloat1622float2(p1);
    return make_float4(f0.x, f0.y, f1.x, f1.y);
}

__global__ __launch_bounds__(256)
void gather_kernel(const int* __restrict__ rowptr, const int* __restrict__ adj,
                   const float* __restrict__ dis, const __nv_bfloat16* __restrict__ src,
                   const float* __restrict__ bias, float* __restrict__ outp,
                   int ldc, int n) {
    int node = (blockIdx.x * blockDim.x + threadIdx.x) >> 5;
    int lane = threadIdx.x & 31;
    if (node >= n) return;
    int s = rowptr[node];
    int e = rowptr[node + 1];
    const __nv_bfloat16* base = src + lane * 4;
    float ax = 0.f, ay = 0.f, az = 0.f, aw = 0.f;
#pragma unroll 4
    for (int i = s; i < e; i++) {
        int r = __ldg(&adj[i]);
        float nr = __ldg(&dis[r]);
        uint2 u = *reinterpret_cast<const uint2*>(base + (size_t)r * 128);
        float4 v = bf4_to_f4(u);
        ax = fmaf(v.x, nr, ax);
        ay = fmaf(v.y, nr, ay);
        az = fmaf(v.z, nr, az);
        aw = fmaf(v.w, nr, aw);
    }
    float dc = dis[node];
    float4 b = *reinterpret_cast<const float4*>(bias + lane * 4);
    float4 o;
    o.x = fmaf(ax, dc, b.x);
    o.y = fmaf(ay, dc, b.y);
    o.z = fmaf(az, dc, b.z);
    o.w = fmaf(aw, dc, b.w);
    *reinterpret_cast<float4*>(outp + (size_t)node * ldc + lane * 4) = o;
}

// ---------------- log_softmax over 40 logits, one warp per row ----------------
__global__ void logsoftmax_kernel(const float* __restrict__ logits, float* __restrict__ out, int M) {
    int warp = (blockIdx.x * blockDim.x + threadIdx.x) >> 5;
    int lane = threadIdx.x & 31;
    if (warp >= M) return;
    const float* L = logits + (size_t)warp * NCLS;
    float v0 = L[lane];
    float v1 = (lane < NCLS - 32) ? L[32 + lane] : -INFINITY;
    float m = fmaxf(v0, v1);
#pragma unroll
    for (int o = 16; o > 0; o >>= 1) m = fmaxf(m, __shfl_xor_sync(0xffffffffu, m, o));
    float s = expf(v0 - m) + ((lane < NCLS - 32) ? expf(v1 - m) : 0.f);
#pragma unroll
    for (int o = 16; o > 0; o >>= 1) s += __shfl_xor_sync(0xffffffffu, s, o);
    float ls = logf(s);
    float* O = out + (size_t)warp * NCLS;
    O[lane] = v0 - m - ls;
    if (lane < NCLS - 32) O[32 + lane] = v1 - m - ls;
}

// ---------------- host launcher ----------------
extern "C" void kernel_launch(void* const* d_in, const int* in_sizes, int n_in,
                              void* d_out, int out_size) {
    const float* x       = (const float*)d_in[0];
    const int*   ei1     = (const int*)  d_in[1];
    const int*   ei2     = (const int*)  d_in[2];
    const float* W_lin1  = (const float*)d_in[3];
    const float* b_lin1  = (const float*)d_in[4];
    const float* W_c1    = (const float*)d_in[5];
    const float* b_c1    = (const float*)d_in[6];
    const float* W_c2    = (const float*)d_in[7];
    const float* b_c2    = (const float*)d_in[8];
    const float* W_lin2  = (const float*)d_in[9];
    const float* b_lin2  = (const float*)d_in[10];
    float* out = (float*)d_out;

    const int E1 = in_sizes[1] / 2;
    const int E2 = in_sizes[2] / 2;
    const int n  = NNODES;

    __nv_bfloat16* p_hwh;
    float *p_final, *p_logits, *p_dis1, *p_dis2;
    int *p_cnt1, *p_cnt2, *p_rp1, *p_rp2, *p_cur1, *p_cur2, *p_adj1, *p_adj2;
    cudaGetSymbolAddress((void**)&p_hwh,    g_hwh);
    cudaGetSymbolAddress((void**)&p_final,  g_final);
    cudaGetSymbolAddress((void**)&p_logits, g_logits);
    cudaGetSymbolAddress((void**)&p_dis1,   g_dis1);
    cudaGetSymbolAddress((void**)&p_dis2,   g_dis2);
    cudaGetSymbolAddress((void**)&p_cnt1,   g_cnt1);
    cudaGetSymbolAddress((void**)&p_cnt2,   g_cnt2);
    cudaGetSymbolAddress((void**)&p_rp1,    g_rowptr1);
    cudaGetSymbolAddress((void**)&p_rp2,    g_rowptr2);
    cudaGetSymbolAddress((void**)&p_cur1,   g_cursor1);
    cudaGetSymbolAddress((void**)&p_cur2,   g_cursor2);
    cudaGetSymbolAddress((void**)&p_adj1,   g_adj1);
    cudaGetSymbolAddress((void**)&p_adj2,   g_adj2);

    // ---- CSR build (4 launches) ----
    zero2_kernel<<<(n + 255) / 256, 256>>>(p_cnt1, p_cnt2, n);
    hist2_kernel<<<(E1 + E2 + 255) / 256, 256>>>(ei1, E1, p_cnt1, ei2, E2, p_cnt2);
    scan2_kernel<<<2, 1024>>>(p_cnt1, p_rp1, p_cur1, p_dis1, p_cnt2, p_rp2, p_cur2, p_dis2, n);
    fill2_kernel<<<(E1 + E2 + 255) / 256, 256>>>(ei1, E1, p_cur1, p_adj1, ei2, E2, p_cur2, p_adj2);

    const int gy = (n + 127) / 128;  // 391
    const int gather_grid = (n * 32 + 255) / 256;

    // ---- h = relu(x @ W_lin1 + b_lin1) -> final[:, 0:256] ----
    mma_gemm_kernel<128, true, true, false><<<dim3(H0 / 128, gy), 256>>>(
        x, F_IN, W_lin1, b_lin1, p_final, DFIN, n, H0, F_IN);

    // ---- hw(bf16) = h @ W_c1 ----
    mma_gemm_kernel<128, false, false, true><<<dim3(1, gy), 256>>>(
        p_final, DFIN, W_c1, nullptr, p_hwh, H1, n, H1, H0);

    // ---- layer-1 gathers -> final[:, 256:384], final[:, 384:512] (bias fused) ----
    gather_kernel<<<gather_grid, 256>>>(p_rp1, p_adj1, p_dis1, p_hwh, b_c1, p_final + 256, DFIN, n);
    gather_kernel<<<gather_grid, 256>>>(p_rp2, p_adj2, p_dis2, p_hwh, b_c1, p_final + 384, DFIN, n);

    // ---- hw(bf16) = R1 @ W_c2  (R1 = final[:, 256:512]) ----
    mma_gemm_kernel<128, false, false, true><<<dim3(1, gy), 256>>>(
        p_final + 256, DFIN, W_c2, nullptr, p_hwh, H2, n, H2, 2 * H1);

    // ---- layer-2 gathers -> final[:, 512:640], final[:, 640:768] ----
    gather_kernel<<<gather_grid, 256>>>(p_rp1, p_adj1, p_dis1, p_hwh, b_c2, p_final + 512, DFIN, n);
    gather_kernel<<<gather_grid, 256>>>(p_rp2, p_adj2, p_dis2, p_hwh, b_c2, p_final + 640, DFIN, n);

    // ---- logits = final @ W_lin2 + b_lin2 (BN=64 tile for N=40) ----
    mma_gemm_kernel<64, false, true, false><<<dim3(1, gy), 256>>>(
        p_final, DFIN, W_lin2, b_lin2, p_logits, NCLS, n, NCLS, DFIN);

    // ---- log_softmax -> out ----
    logsoftmax_kernel<<<(n + 7) / 8, 256>>>(p_logits, out, n);
}

// round 6
// speedup vs baseline: 2.9249x; 1.1059x over previous
#include <cuda_runtime.h>
#include <cuda_bf16.h>
#include <cstdint>
#include <math.h>

// ---------------- problem constants ----------------
#define NNODES 50000
#define F_IN   512
#define H0     256
#define H1     128
#define H2     128
#define NCLS   40
#define DFIN   768
#define E1MAX  800000
#define E2MAX  1600000

// ---------------- static scratch ----------------
__device__ __nv_bfloat16 g_hwh[(size_t)NNODES * H1];  // bf16 message buffer
__device__ float g_final[(size_t)NNODES * DFIN];
__device__ float g_dis1[NNODES];
__device__ float g_dis2[NNODES];
__device__ int   g_cnt1[NNODES];
__device__ int   g_cnt2[NNODES];
__device__ int   g_rowptr1[NNODES + 1];
__device__ int   g_rowptr2[NNODES + 1];
__device__ int   g_cursor1[NNODES];
__device__ int   g_cursor2[NNODES];
__device__ int   g_adj1[E1MAX];
__device__ int   g_adj2[E2MAX];

// ---------------- CSR build (merged kernels) ----------------
__global__ void zero2_kernel(int* __restrict__ p1, int* __restrict__ p2, int n) {
    int i = blockIdx.x * blockDim.x + threadIdx.x;
    if (i < n) { p1[i] = 0; p2[i] = 0; }
}

__global__ void hist2_kernel(const int* __restrict__ ei1, int E1, int* __restrict__ cnt1,
                             const int* __restrict__ ei2, int E2, int* __restrict__ cnt2) {
    int i = blockIdx.x * blockDim.x + threadIdx.x;
    if (i < E1) {
        atomicAdd(&cnt1[ei1[E1 + i]], 1);
    } else if (i < E1 + E2) {
        int j = i - E1;
        atomicAdd(&cnt2[ei2[E2 + j]], 1);
    }
}

__global__ __launch_bounds__(1024)
void scan2_kernel(int* __restrict__ cnt1, int* __restrict__ rp1, int* __restrict__ cur1, float* __restrict__ dis1,
                  int* __restrict__ cnt2, int* __restrict__ rp2, int* __restrict__ cur2, float* __restrict__ dis2,
                  int n) {
    const int* cnt = (blockIdx.x == 0) ? cnt1 : cnt2;
    int* rowptr    = (blockIdx.x == 0) ? rp1  : rp2;
    int* cursor    = (blockIdx.x == 0) ? cur1 : cur2;
    float* dis     = (blockIdx.x == 0) ? dis1 : dis2;
    __shared__ int part[1024];
    const int t = threadIdx.x;
    const int chunk = (n + 1023) / 1024;
    const int s0 = min(t * chunk, n);
    const int s1 = min(s0 + chunk, n);
    int sum = 0;
    for (int i = s0; i < s1; i++) sum += cnt[i];
    part[t] = sum;
    __syncthreads();
    for (int off = 1; off < 1024; off <<= 1) {
        int v = part[t];
        int o = (t >= off) ? part[t - off] : 0;
        __syncthreads();
        part[t] = v + o;
        __syncthreads();
    }
    int run = (t == 0) ? 0 : part[t - 1];
    for (int i = s0; i < s1; i++) {
        rowptr[i] = run;
        cursor[i] = run;
        int c = cnt[i];
        dis[i] = (c > 0) ? rsqrtf((float)c) : 0.f;
        run += c;
    }
    if (t == 1023) rowptr[n] = part[1023];
}

__global__ void fill2_kernel(const int* __restrict__ ei1, int E1, int* __restrict__ cur1, int* __restrict__ adj1,
                             const int* __restrict__ ei2, int E2, int* __restrict__ cur2, int* __restrict__ adj2) {
    int i = blockIdx.x * blockDim.x + threadIdx.x;
    if (i < E1) {
        int slot = atomicAdd(&cur1[ei1[E1 + i]], 1);
        adj1[slot] = ei1[i];
    } else if (i < E1 + E2) {
        int j = i - E1;
        int slot = atomicAdd(&cur2[ei2[E2 + j]], 1);
        adj2[slot] = ei2[j];
    }
}

// ---------------- MMA helper ----------------
__device__ __forceinline__ void mma_tf32(float* c, const uint32_t* a, uint32_t b0, uint32_t b1) {
    asm volatile(
        "mma.sync.aligned.m16n8k8.row.col.f32.tf32.tf32.f32 "
        "{%0,%1,%2,%3}, {%4,%5,%6,%7}, {%8,%9}, {%0,%1,%2,%3};"
        : "+f"(c[0]), "+f"(c[1]), "+f"(c[2]), "+f"(c[3])
        : "r"(a[0]), "r"(a[1]), "r"(a[2]), "r"(a[3]), "r"(b0), "r"(b1));
}

__device__ __forceinline__ void cp16(uint32_t saddr, const void* gaddr, int srcsz) {
    asm volatile("cp.async.cg.shared.global [%0], [%1], 16, %2;"
                 :: "r"(saddr), "l"(gaddr), "r"(srcsz));
}

// ---------------- TF32 tensor-core GEMM, cp.async double-buffered ----------------
// BM=128, BN in {128, 64}; 8 warps. mma consumes raw fp32 bits (HW truncates to tf32).
// OUTBF: write C as bf16. SOFTMAX: fused log_softmax over NCLS cols, write out directly.
// Softmax staging buffer (Ls) is UNION-overlaid on the pipeline buffers (used only
// after the mainloop, separated by __syncthreads).
template <int BN, bool RELU, bool BIAS, bool OUTBF, bool SOFTMAX>
__global__ __launch_bounds__(256)
void mma_gemm_kernel(const float* __restrict__ A, int lda,
                     const float* __restrict__ B,
                     const float* __restrict__ bias,
                     void* __restrict__ Cv, int ldc,
                     int M, int N, int K) {
    constexpr int MI = (BN == 128) ? 4 : 2;
    struct Pipe {
        float As[2][128][20];
        float Bs[2][16][BN + 8];
    };
    union Smem {
        Pipe p;
        float Ls[128][44];
    };
    __shared__ Smem smem;
    auto& As = smem.p.As;
    auto& Bs = smem.p.Bs;

    const int tid  = threadIdx.x;
    const int lane = tid & 31;
    const int warp = tid >> 5;
    const int bm0 = blockIdx.y * 128;
    const int bn0 = blockIdx.x * BN;
    const int wm = (BN == 128) ? (warp & 1) * 64 : (warp & 3) * 32;
    const int wn = (BN == 128) ? (warp >> 1) * 32 : (warp >> 2) * 32;
    const int g  = lane >> 2;
    const int tg = lane & 3;

    float acc[MI][4][4];
#pragma unroll
    for (int i = 0; i < MI; i++)
#pragma unroll
        for (int j = 0; j < 4; j++)
#pragma unroll
            for (int q = 0; q < 4; q++) acc[i][j][q] = 0.f;

    // A tile: 128 rows x 16 floats; each thread owns 8 consecutive floats (2x cp.async)
    const int aRow = tid >> 1;
    const int aH   = (tid & 1) * 8;
    const int aSz  = ((bm0 + aRow) < M) ? 16 : 0;
    const float* Aptr = A + (size_t)(bm0 + aRow) * lda + aH;

    // B tile: 16 rows x BN floats. BN=128: 2 float4/thread; BN=64: 1 float4/thread.
    const int bRow = (BN == 128) ? (tid >> 5) : (tid >> 4);
    const int bC4  = (BN == 128) ? (tid & 31) * 4 : (tid & 15) * 4;
    const int bSz  = ((bn0 + bC4) < N) ? 16 : 0;
    const float* Bptr = B + (size_t)bRow * N + bn0 + bC4;

    const int ntiles = K / 16;

    auto load_tile = [&](int t, int b) {
        const int k0 = t * 16;
        uint32_t sa = (uint32_t)__cvta_generic_to_shared(&As[b][aRow][aH]);
        cp16(sa,      Aptr + k0,     aSz);
        cp16(sa + 16, Aptr + k0 + 4, aSz);
        uint32_t sb = (uint32_t)__cvta_generic_to_shared(&Bs[b][bRow][bC4]);
        cp16(sb, Bptr + (size_t)k0 * N, bSz);
        if (BN == 128) {
            uint32_t sb1 = (uint32_t)__cvta_generic_to_shared(&Bs[b][bRow + 8][bC4]);
            cp16(sb1, Bptr + (size_t)(k0 + 8) * N, bSz);
        }
    };

    load_tile(0, 0);
    asm volatile("cp.async.commit_group;");

    const int lm_row = wm + (lane & 7) + ((lane >> 3) & 1) * 8;
    const int lm_kq  = (lane >> 4) * 4;

    int buf = 0;
    for (int t = 0; t < ntiles; t++) {
        asm volatile("cp.async.wait_group 0;" ::: "memory");
        __syncthreads();
        if (t + 1 < ntiles) {
            load_tile(t + 1, buf ^ 1);
            asm volatile("cp.async.commit_group;");
        }
#pragma unroll
        for (int kk = 0; kk < 16; kk += 8) {
            uint32_t af[MI][4];
#pragma unroll
            for (int mi = 0; mi < MI; mi++) {
                uint32_t saddr = (uint32_t)__cvta_generic_to_shared(
                    &As[buf][lm_row + mi * 16][kk + lm_kq]);
                asm volatile("ldmatrix.sync.aligned.m8n8.x4.shared.b16 {%0,%1,%2,%3}, [%4];"
                             : "=r"(af[mi][0]), "=r"(af[mi][1]), "=r"(af[mi][2]), "=r"(af[mi][3])
                             : "r"(saddr));
            }
#pragma unroll
            for (int nj = 0; nj < 4; nj++) {
                uint32_t b0 = __float_as_uint(Bs[buf][kk + tg][wn + nj * 8 + g]);
                uint32_t b1 = __float_as_uint(Bs[buf][kk + 4 + tg][wn + nj * 8 + g]);
#pragma unroll
                for (int mi = 0; mi < MI; mi++) {
                    mma_tf32(acc[mi][nj], af[mi], b0, b1);
                }
            }
        }
        buf ^= 1;
    }

    if (SOFTMAX) {
        // all mainloop smem reads done; re-use smem as logits staging buffer
        __syncthreads();
        auto& Ls = smem.Ls;
#pragma unroll
        for (int nj = 0; nj < 4; nj++) {
            const int col = bn0 + wn + nj * 8 + tg * 2;
            if (col >= NCLS) continue;
            float b0 = bias[col], b1 = bias[col + 1];
#pragma unroll
            for (int mi = 0; mi < MI; mi++) {
                const int r0 = wm + mi * 16 + g;
                Ls[r0][col]         = acc[mi][nj][0] + b0;
                Ls[r0][col + 1]     = acc[mi][nj][1] + b1;
                Ls[r0 + 8][col]     = acc[mi][nj][2] + b0;
                Ls[r0 + 8][col + 1] = acc[mi][nj][3] + b1;
            }
        }
        __syncthreads();
        float* O = (float*)Cv;
#pragma unroll
        for (int rr = 0; rr < 16; rr++) {
            const int r = warp * 16 + rr;
            const int grow = bm0 + r;
            if (grow >= M) break;
            float v0 = Ls[r][lane];
            float v1 = (lane < NCLS - 32) ? Ls[r][32 + lane] : -INFINITY;
            float m = fmaxf(v0, v1);
#pragma unroll
            for (int o = 16; o > 0; o >>= 1) m = fmaxf(m, __shfl_xor_sync(0xffffffffu, m, o));
            float s = expf(v0 - m) + ((lane < NCLS - 32) ? expf(v1 - m) : 0.f);
#pragma unroll
            for (int o = 16; o > 0; o >>= 1) s += __shfl_xor_sync(0xffffffffu, s, o);
            float ls = logf(s);
            O[(size_t)grow * NCLS + lane] = v0 - m - ls;
            if (lane < NCLS - 32) O[(size_t)grow * NCLS + 32 + lane] = v1 - m - ls;
        }
    } else {
#pragma unroll
        for (int nj = 0; nj < 4; nj++) {
            const int col = bn0 + wn + nj * 8 + tg * 2;
            if (col >= N) continue;
            float b0 = 0.f, b1 = 0.f;
            if (BIAS) { b0 = bias[col]; b1 = bias[col + 1]; }
#pragma unroll
            for (int mi = 0; mi < MI; mi++) {
                const int row0 = bm0 + wm + mi * 16 + g;
                float v0 = acc[mi][nj][0] + b0;
                float v1 = acc[mi][nj][1] + b1;
                float v2 = acc[mi][nj][2] + b0;
                float v3 = acc[mi][nj][3] + b1;
                if (RELU) {
                    v0 = fmaxf(v0, 0.f); v1 = fmaxf(v1, 0.f);
                    v2 = fmaxf(v2, 0.f); v3 = fmaxf(v3, 0.f);
                }
                if (OUTBF) {
                    __nv_bfloat16* C = (__nv_bfloat16*)Cv;
                    if (row0 < M) {
                        *reinterpret_cast<__nv_bfloat162*>(C + (size_t)row0 * ldc + col) =
                            __floats2bfloat162_rn(v0, v1);
                    }
                    if (row0 + 8 < M) {
                        *reinterpret_cast<__nv_bfloat162*>(C + (size_t)(row0 + 8) * ldc + col) =
                            __floats2bfloat162_rn(v2, v3);
                    }
                } else {
                    float* C = (float*)Cv;
                    if (row0 < M) {
                        *reinterpret_cast<float2*>(C + (size_t)row0 * ldc + col) = make_float2(v0, v1);
                    }
                    if (row0 + 8 < M) {
                        *reinterpret_cast<float2*>(C + (size_t)(row0 + 8) * ldc + col) = make_float2(v2, v3);
                    }
                }
            }
        }
    }
}

// ---------------- merged dual-CSR gather (bf16 source): one warp per (set,node) ----------------
__device__ __forceinline__ float4 bf4_to_f4(uint2 u) {
    __nv_bfloat162 p0 = *reinterpret_cast<__nv_bfloat162*>(&u.x);
    __nv_bfloat162 p1 = *reinterpret_cast<__nv_bfloat162*>(&u.y);
    float2 f0 = __bfloat1622float2(p0);
    float2 f1 = __bfloat1622float2(p1);
    return make_float4(f0.x, f0.y, f1.x, f1.y);
}

__global__ __launch_bounds__(256)
void gather2_kernel(const int* __restrict__ rp1, const int* __restrict__ adj1, const float* __restrict__ dis1,
                    const int* __restrict__ rp2, const int* __restrict__ adj2, const float* __restrict__ dis2,
                    const __nv_bfloat16* __restrict__ src, const float* __restrict__ bias,
                    float* __restrict__ fin, int off1, int off2, int n) {
    int gw = (blockIdx.x * blockDim.x + threadIdx.x) >> 5;
    int lane = threadIdx.x & 31;
    if (gw >= 2 * n) return;
    const bool second = (gw >= n);
    const int node = second ? gw - n : gw;
    const int* rowptr = second ? rp2 : rp1;
    const int* adj    = second ? adj2 : adj1;
    const float* dis  = second ? dis2 : dis1;
    float* outp = fin + (second ? off2 : off1);

    int s = rowptr[node];
    int e = rowptr[node + 1];
    const __nv_bfloat16* base = src + lane * 4;
    float ax = 0.f, ay = 0.f, az = 0.f, aw = 0.f;
#pragma unroll 4
    for (int i = s; i < e; i++) {
        int r = __ldg(&adj[i]);
        float nr = __ldg(&dis[r]);
        uint2 u = *reinterpret_cast<const uint2*>(base + (size_t)r * 128);
        float4 v = bf4_to_f4(u);
        ax = fmaf(v.x, nr, ax);
        ay = fmaf(v.y, nr, ay);
        az = fmaf(v.z, nr, az);
        aw = fmaf(v.w, nr, aw);
    }
    float dc = dis[node];
    float4 b = *reinterpret_cast<const float4*>(bias + lane * 4);
    float4 o;
    o.x = fmaf(ax, dc, b.x);
    o.y = fmaf(ay, dc, b.y);
    o.z = fmaf(az, dc, b.z);
    o.w = fmaf(aw, dc, b.w);
    *reinterpret_cast<float4*>(outp + (size_t)node * DFIN + lane * 4) = o;
}

// ---------------- host launcher ----------------
extern "C" void kernel_launch(void* const* d_in, const int* in_sizes, int n_in,
                              void* d_out, int out_size) {
    const float* x       = (const float*)d_in[0];
    const int*   ei1     = (const int*)  d_in[1];
    const int*   ei2     = (const int*)  d_in[2];
    const float* W_lin1  = (const float*)d_in[3];
    const float* b_lin1  = (const float*)d_in[4];
    const float* W_c1    = (const float*)d_in[5];
    const float* b_c1    = (const float*)d_in[6];
    const float* W_c2    = (const float*)d_in[7];
    const float* b_c2    = (const float*)d_in[8];
    const float* W_lin2  = (const float*)d_in[9];
    const float* b_lin2  = (const float*)d_in[10];
    float* out = (float*)d_out;

    const int E1 = in_sizes[1] / 2;
    const int E2 = in_sizes[2] / 2;
    const int n  = NNODES;

    __nv_bfloat16* p_hwh;
    float *p_final, *p_dis1, *p_dis2;
    int *p_cnt1, *p_cnt2, *p_rp1, *p_rp2, *p_cur1, *p_cur2, *p_adj1, *p_adj2;
    cudaGetSymbolAddress((void**)&p_hwh,    g_hwh);
    cudaGetSymbolAddress((void**)&p_final,  g_final);
    cudaGetSymbolAddress((void**)&p_dis1,   g_dis1);
    cudaGetSymbolAddress((void**)&p_dis2,   g_dis2);
    cudaGetSymbolAddress((void**)&p_cnt1,   g_cnt1);
    cudaGetSymbolAddress((void**)&p_cnt2,   g_cnt2);
    cudaGetSymbolAddress((void**)&p_rp1,    g_rowptr1);
    cudaGetSymbolAddress((void**)&p_rp2,    g_rowptr2);
    cudaGetSymbolAddress((void**)&p_cur1,   g_cursor1);
    cudaGetSymbolAddress((void**)&p_cur2,   g_cursor2);
    cudaGetSymbolAddress((void**)&p_adj1,   g_adj1);
    cudaGetSymbolAddress((void**)&p_adj2,   g_adj2);

    // lazy-init side stream + fork/join events (created on first, non-captured call)
    static cudaStream_t s2 = nullptr;
    static cudaEvent_t evFork = nullptr, evJoin = nullptr;
    if (s2 == nullptr) {
        cudaStreamCreateWithFlags(&s2, cudaStreamNonBlocking);
        cudaEventCreateWithFlags(&evFork, cudaEventDisableTiming);
        cudaEventCreateWithFlags(&evJoin, cudaEventDisableTiming);
    }

    // ---- fork: CSR build on s2, overlapped with GEMM1/GEMM2 on main stream ----
    cudaEventRecord(evFork, 0);
    cudaStreamWaitEvent(s2, evFork, 0);
    zero2_kernel<<<(n + 255) / 256, 256, 0, s2>>>(p_cnt1, p_cnt2, n);
    hist2_kernel<<<(E1 + E2 + 255) / 256, 256, 0, s2>>>(ei1, E1, p_cnt1, ei2, E2, p_cnt2);
    scan2_kernel<<<2, 1024, 0, s2>>>(p_cnt1, p_rp1, p_cur1, p_dis1, p_cnt2, p_rp2, p_cur2, p_dis2, n);
    fill2_kernel<<<(E1 + E2 + 255) / 256, 256, 0, s2>>>(ei1, E1, p_cur1, p_adj1, ei2, E2, p_cur2, p_adj2);
    cudaEventRecord(evJoin, s2);

    const int gy = (n + 127) / 128;  // 391
    const int gather2_grid = (2 * n * 32 + 255) / 256;

    // ---- h = relu(x @ W_lin1 + b_lin1) -> final[:, 0:256] ----
    mma_gemm_kernel<128, true, true, false, false><<<dim3(H0 / 128, gy), 256>>>(
        x, F_IN, W_lin1, b_lin1, p_final, DFIN, n, H0, F_IN);

    // ---- hw(bf16) = h @ W_c1 ----
    mma_gemm_kernel<128, false, false, true, false><<<dim3(1, gy), 256>>>(
        p_final, DFIN, W_c1, nullptr, p_hwh, H1, n, H1, H0);

    // ---- join: gathers need CSR ----
    cudaStreamWaitEvent(0, evJoin, 0);

    // ---- layer-1 gathers (both edge sets, one launch) -> final[:,256:384],[:,384:512] ----
    gather2_kernel<<<gather2_grid, 256>>>(p_rp1, p_adj1, p_dis1, p_rp2, p_adj2, p_dis2,
                                          p_hwh, b_c1, p_final, 256, 384, n);

    // ---- hw(bf16) = R1 @ W_c2  (R1 = final[:, 256:512]) ----
    mma_gemm_kernel<128, false, false, true, false><<<dim3(1, gy), 256>>>(
        p_final + 256, DFIN, W_c2, nullptr, p_hwh, H2, n, H2, 2 * H1);

    // ---- layer-2 gathers -> final[:,512:640],[:,640:768] ----
    gather2_kernel<<<gather2_grid, 256>>>(p_rp1, p_adj1, p_dis1, p_rp2, p_adj2, p_dis2,
                                          p_hwh, b_c2, p_final, 512, 640, n);

    // ---- logits = final @ W_lin2 + b_lin2, fused log_softmax -> out ----
    mma_gemm_kernel<64, false, true, false, true><<<dim3(1, gy), 256>>>(
        p_final, DFIN, W_lin2, b_lin2, out, NCLS, n, NCLS, DFIN);
}

// round 7
// speedup vs baseline: 3.8624x; 1.3205x over previous
#include <cuda_runtime.h>
#include <cuda_bf16.h>
#include <cstdint>
#include <math.h>

// ---------------- problem constants ----------------
#define NNODES 50000
#define F_IN   512
#define H0     256
#define H1     128
#define H2     128
#define NCLS   40
#define DFIN   768
#define E1MAX  800000
#define E2MAX  1600000

// ---------------- static scratch ----------------
__device__ __nv_bfloat16 g_hwh[(size_t)NNODES * H1];    // bf16 message buffer
__device__ __nv_bfloat16 g_final[(size_t)NNODES * DFIN]; // bf16 concat buffer
__device__ __nv_bfloat16 g_w1[F_IN * H0];
__device__ __nv_bfloat16 g_wc1[H0 * H1];
__device__ __nv_bfloat16 g_wc2[2 * H1 * H2];
__device__ __nv_bfloat16 g_w2[DFIN * NCLS];
__device__ float g_dis1[NNODES];
__device__ float g_dis2[NNODES];
__device__ int   g_cnt1[NNODES];
__device__ int   g_cnt2[NNODES];
__device__ int   g_rowptr1[NNODES + 1];
__device__ int   g_rowptr2[NNODES + 1];
__device__ int   g_cursor1[NNODES];
__device__ int   g_cursor2[NNODES];
__device__ int   g_adj1[E1MAX];
__device__ int   g_adj2[E2MAX];

// ---------------- weight conversion fp32 -> bf16 ----------------
__global__ void cvt_weights_kernel(const float* __restrict__ w1, const float* __restrict__ wc1,
                                   const float* __restrict__ wc2, const float* __restrict__ w2,
                                   __nv_bfloat16* __restrict__ o1, __nv_bfloat16* __restrict__ oc1,
                                   __nv_bfloat16* __restrict__ oc2, __nv_bfloat16* __restrict__ o2) {
    const int S1 = F_IN * H0, S2 = H0 * H1, S3 = 2 * H1 * H2, S4 = DFIN * NCLS;
    int i = blockIdx.x * blockDim.x + threadIdx.x;
    int total = S1 + S2 + S3 + S4;
    for (; i < total; i += gridDim.x * blockDim.x) {
        if (i < S1) o1[i] = __float2bfloat16_rn(w1[i]);
        else if (i < S1 + S2) oc1[i - S1] = __float2bfloat16_rn(wc1[i - S1]);
        else if (i < S1 + S2 + S3) oc2[i - S1 - S2] = __float2bfloat16_rn(wc2[i - S1 - S2]);
        else o2[i - S1 - S2 - S3] = __float2bfloat16_rn(w2[i - S1 - S2 - S3]);
    }
}

// ---------------- CSR build ----------------
__global__ void zero2_kernel(int* __restrict__ p1, int* __restrict__ p2, int n) {
    int i = blockIdx.x * blockDim.x + threadIdx.x;
    if (i < n) { p1[i] = 0; p2[i] = 0; }
}

__global__ void hist2_kernel(const int* __restrict__ ei1, int E1, int* __restrict__ cnt1,
                             const int* __restrict__ ei2, int E2, int* __restrict__ cnt2) {
    int i = blockIdx.x * blockDim.x + threadIdx.x;
    if (i < E1) {
        atomicAdd(&cnt1[ei1[E1 + i]], 1);
    } else if (i < E1 + E2) {
        int j = i - E1;
        atomicAdd(&cnt2[ei2[E2 + j]], 1);
    }
}

__global__ __launch_bounds__(1024)
void scan2_kernel(int* __restrict__ cnt1, int* __restrict__ rp1, int* __restrict__ cur1, float* __restrict__ dis1,
                  int* __restrict__ cnt2, int* __restrict__ rp2, int* __restrict__ cur2, float* __restrict__ dis2,
                  int n) {
    const int* cnt = (blockIdx.x == 0) ? cnt1 : cnt2;
    int* rowptr    = (blockIdx.x == 0) ? rp1  : rp2;
    int* cursor    = (blockIdx.x == 0) ? cur1 : cur2;
    float* dis     = (blockIdx.x == 0) ? dis1 : dis2;
    __shared__ int part[1024];
    const int t = threadIdx.x;
    const int chunk = (n + 1023) / 1024;
    const int s0 = min(t * chunk, n);
    const int s1 = min(s0 + chunk, n);
    int sum = 0;
    for (int i = s0; i < s1; i++) sum += cnt[i];
    part[t] = sum;
    __syncthreads();
    for (int off = 1; off < 1024; off <<= 1) {
        int v = part[t];
        int o = (t >= off) ? part[t - off] : 0;
        __syncthreads();
        part[t] = v + o;
        __syncthreads();
    }
    int run = (t == 0) ? 0 : part[t - 1];
    for (int i = s0; i < s1; i++) {
        rowptr[i] = run;
        cursor[i] = run;
        int c = cnt[i];
        dis[i] = (c > 0) ? rsqrtf((float)c) : 0.f;
        run += c;
    }
    if (t == 1023) rowptr[n] = part[1023];
}

__global__ void fill2_kernel(const int* __restrict__ ei1, int E1, int* __restrict__ cur1, int* __restrict__ adj1,
                             const int* __restrict__ ei2, int E2, int* __restrict__ cur2, int* __restrict__ adj2) {
    int i = blockIdx.x * blockDim.x + threadIdx.x;
    if (i < E1) {
        int slot = atomicAdd(&cur1[ei1[E1 + i]], 1);
        adj1[slot] = ei1[i];
    } else if (i < E1 + E2) {
        int j = i - E1;
        int slot = atomicAdd(&cur2[ei2[E2 + j]], 1);
        adj2[slot] = ei2[j];
    }
}

// ---------------- helpers ----------------
__device__ __forceinline__ void mma_bf16(float* c, const uint32_t* a, uint32_t b0, uint32_t b1) {
    asm volatile(
        "mma.sync.aligned.m16n8k16.row.col.f32.bf16.bf16.f32 "
        "{%0,%1,%2,%3}, {%4,%5,%6,%7}, {%8,%9}, {%0,%1,%2,%3};"
        : "+f"(c[0]), "+f"(c[1]), "+f"(c[2]), "+f"(c[3])
        : "r"(a[0]), "r"(a[1]), "r"(a[2]), "r"(a[3]), "r"(b0), "r"(b1));
}

__device__ __forceinline__ void cp16(uint32_t saddr, const void* gaddr, int srcsz) {
    asm volatile("cp.async.cg.shared.global [%0], [%1], 16, %2;"
                 :: "r"(saddr), "l"(gaddr), "r"(srcsz));
}

__device__ __forceinline__ uint32_t packbf(float a, float b) {
    __nv_bfloat162 h = __floats2bfloat162_rn(a, b);
    return *reinterpret_cast<uint32_t*>(&h);
}

// ---------------- bf16 tensor-core GEMM, cp.async double-buffered ----------------
// BM=128, BK=32, BN in {128, 64}; 8 warps; mma m16n8k16 bf16, fp32 accumulate.
// ACONV: A is fp32 in gmem (converted to bf16 via reg staging). Else A is bf16.
// Output: bf16 (C, ldc). SOFTMAX: fused log_softmax over NCLS cols -> fp32 out.
template <int BN, bool RELU, bool BIAS, bool ACONV, bool SOFTMAX>
__global__ __launch_bounds__(256)
void mma_gemm_bf16(const void* __restrict__ Av, int lda,
                   const __nv_bfloat16* __restrict__ B,
                   const float* __restrict__ bias,
                   void* __restrict__ Cv, int ldc,
                   int M, int N, int K) {
    constexpr int MI = (BN == 128) ? 4 : 2;
    constexpr int BK = 32;
    struct Pipe {
        __nv_bfloat16 As[2][128][BK + 8];   // stride 40 bf16 = 20 banks
        __nv_bfloat16 Bs[2][BK][BN + 8];    // stride (BN+8) bf16 = 68/36 banks
    };
    union Smem {
        Pipe p;
        float Ls[128][44];
    };
    __shared__ Smem smem;
    auto& As = smem.p.As;
    auto& Bs = smem.p.Bs;

    const int tid  = threadIdx.x;
    const int lane = tid & 31;
    const int warp = tid >> 5;
    const int bm0 = blockIdx.y * 128;
    const int bn0 = blockIdx.x * BN;
    const int wm = (BN == 128) ? (warp & 1) * 64 : (warp & 3) * 32;
    const int wn = (BN == 128) ? (warp >> 1) * 32 : (warp >> 2) * 32;
    const int g  = lane >> 2;
    const int tg = lane & 3;

    float acc[MI][4][4];
#pragma unroll
    for (int i = 0; i < MI; i++)
#pragma unroll
        for (int j = 0; j < 4; j++)
#pragma unroll
            for (int q = 0; q < 4; q++) acc[i][j][q] = 0.f;

    // A tile: 128 rows x 32 elements; each thread owns 16 consecutive elements
    const int aRow = tid >> 1;
    const int aEl  = (tid & 1) * 16;
    const bool aValid = (bm0 + aRow) < M;
    const __nv_bfloat16* Ah = ACONV ? nullptr : ((const __nv_bfloat16*)Av + (size_t)(bm0 + aRow) * lda + aEl);
    const float*         Af = ACONV ? ((const float*)Av + (size_t)(bm0 + aRow) * lda + aEl) : nullptr;

    // B tile: 32 rows x BN elements (bf16).
    // BN=128: rows tid/16 and tid/16+16, 16B chunk (tid&15). BN=64: row tid/8, chunk tid&7.
    const int bRow = (BN == 128) ? (tid >> 4) : (tid >> 3);
    const int bEl  = (BN == 128) ? (tid & 15) * 8 : (tid & 7) * 8;
    const int bSz  = ((bn0 + bEl) < N) ? 16 : 0;
    const __nv_bfloat16* Bptr = B + (size_t)bRow * N + bn0 + bEl;

    const int ntiles = K / BK;

    auto loadB = [&](int t, int b) {
        const int k0 = t * BK;
        uint32_t sb = (uint32_t)__cvta_generic_to_shared(&Bs[b][bRow][bEl]);
        cp16(sb, Bptr + (size_t)k0 * N, bSz);
        if (BN == 128) {
            uint32_t sb1 = (uint32_t)__cvta_generic_to_shared(&Bs[b][bRow + 16][bEl]);
            cp16(sb1, Bptr + (size_t)(k0 + 16) * N, bSz);
        }
    };
    auto loadA_cp = [&](int t, int b) {
        const int k0 = t * BK;
        uint32_t sa = (uint32_t)__cvta_generic_to_shared(&As[b][aRow][aEl]);
        cp16(sa,      Ah + k0,     aValid ? 16 : 0);
        cp16(sa + 16, Ah + k0 + 8, aValid ? 16 : 0);
    };
    float4 pa[4];
    auto ldgA = [&](int t) {
        const int k0 = t * BK;
        if (aValid) {
#pragma unroll
            for (int j = 0; j < 4; j++)
                pa[j] = *reinterpret_cast<const float4*>(Af + k0 + j * 4);
        } else {
#pragma unroll
            for (int j = 0; j < 4; j++) pa[j] = make_float4(0.f, 0.f, 0.f, 0.f);
        }
    };
    auto stsA = [&](int b) {
        uint4 u0, u1;
        u0.x = packbf(pa[0].x, pa[0].y); u0.y = packbf(pa[0].z, pa[0].w);
        u0.z = packbf(pa[1].x, pa[1].y); u0.w = packbf(pa[1].z, pa[1].w);
        u1.x = packbf(pa[2].x, pa[2].y); u1.y = packbf(pa[2].z, pa[2].w);
        u1.z = packbf(pa[3].x, pa[3].y); u1.w = packbf(pa[3].z, pa[3].w);
        uint4* d = reinterpret_cast<uint4*>(&As[b][aRow][aEl]);
        d[0] = u0; d[1] = u1;
    };

    // ---- prologue: tile 0 ----
    if (ACONV) ldgA(0);
    loadB(0, 0);
    if (!ACONV) loadA_cp(0, 0);
    asm volatile("cp.async.commit_group;");
    if (ACONV) stsA(0);

    const int lmA_row = wm + (lane & 15);
    const int lmA_col = (lane >> 4) * 8;
    const int lmB_row = lane & 15;
    const int lmB_col = (lane >> 4) * 8;

    int buf = 0;
    for (int t = 0; t < ntiles; t++) {
        asm volatile("cp.async.wait_group 0;" ::: "memory");
        __syncthreads();
        const bool next = (t + 1 < ntiles);
        if (next) {
            loadB(t + 1, buf ^ 1);
            if (!ACONV) loadA_cp(t + 1, buf ^ 1);
            asm volatile("cp.async.commit_group;");
            if (ACONV) ldgA(t + 1);
        }
#pragma unroll
        for (int kk = 0; kk < BK; kk += 16) {
            uint32_t af[MI][4];
#pragma unroll
            for (int mi = 0; mi < MI; mi++) {
                uint32_t saddr = (uint32_t)__cvta_generic_to_shared(
                    &As[buf][lmA_row + mi * 16][kk + lmA_col]);
                asm volatile("ldmatrix.sync.aligned.m8n8.x4.shared.b16 {%0,%1,%2,%3}, [%4];"
                             : "=r"(af[mi][0]), "=r"(af[mi][1]), "=r"(af[mi][2]), "=r"(af[mi][3])
                             : "r"(saddr));
            }
            uint32_t bf[2][4];
#pragma unroll
            for (int nj2 = 0; nj2 < 2; nj2++) {
                uint32_t saddr = (uint32_t)__cvta_generic_to_shared(
                    &Bs[buf][kk + lmB_row][wn + nj2 * 16 + lmB_col]);
                asm volatile("ldmatrix.sync.aligned.m8n8.x4.trans.shared.b16 {%0,%1,%2,%3}, [%4];"
                             : "=r"(bf[nj2][0]), "=r"(bf[nj2][1]), "=r"(bf[nj2][2]), "=r"(bf[nj2][3])
                             : "r"(saddr));
            }
#pragma unroll
            for (int nj = 0; nj < 4; nj++) {
                uint32_t b0 = bf[nj >> 1][(nj & 1) * 2];
                uint32_t b1 = bf[nj >> 1][(nj & 1) * 2 + 1];
#pragma unroll
                for (int mi = 0; mi < MI; mi++) {
                    mma_bf16(acc[mi][nj], af[mi], b0, b1);
                }
            }
        }
        if (next && ACONV) stsA(buf ^ 1);
        buf ^= 1;
    }

    if (SOFTMAX) {
        __syncthreads();
        auto& Ls = smem.Ls;
#pragma unroll
        for (int nj = 0; nj < 4; nj++) {
            const int col = bn0 + wn + nj * 8 + tg * 2;
            if (col >= NCLS) continue;
            float b0 = bias[col], b1 = bias[col + 1];
#pragma unroll
            for (int mi = 0; mi < MI; mi++) {
                const int r0 = wm + mi * 16 + g;
                Ls[r0][col]         = acc[mi][nj][0] + b0;
                Ls[r0][col + 1]     = acc[mi][nj][1] + b1;
                Ls[r0 + 8][col]     = acc[mi][nj][2] + b0;
                Ls[r0 + 8][col + 1] = acc[mi][nj][3] + b1;
            }
        }
        __syncthreads();
        float* O = (float*)Cv;
#pragma unroll
        for (int rr = 0; rr < 16; rr++) {
            const int r = warp * 16 + rr;
            const int grow = bm0 + r;
            if (grow >= M) break;
            float v0 = Ls[r][lane];
            float v1 = (lane < NCLS - 32) ? Ls[r][32 + lane] : -INFINITY;
            float m = fmaxf(v0, v1);
#pragma unroll
            for (int o = 16; o > 0; o >>= 1) m = fmaxf(m, __shfl_xor_sync(0xffffffffu, m, o));
            float s = expf(v0 - m) + ((lane < NCLS - 32) ? expf(v1 - m) : 0.f);
#pragma unroll
            for (int o = 16; o > 0; o >>= 1) s += __shfl_xor_sync(0xffffffffu, s, o);
            float ls = logf(s);
            O[(size_t)grow * NCLS + lane] = v0 - m - ls;
            if (lane < NCLS - 32) O[(size_t)grow * NCLS + 32 + lane] = v1 - m - ls;
        }
    } else {
        __nv_bfloat16* C = (__nv_bfloat16*)Cv;
#pragma unroll
        for (int nj = 0; nj < 4; nj++) {
            const int col = bn0 + wn + nj * 8 + tg * 2;
            if (col >= N) continue;
            float b0 = 0.f, b1 = 0.f;
            if (BIAS) { b0 = bias[col]; b1 = bias[col + 1]; }
#pragma unroll
            for (int mi = 0; mi < MI; mi++) {
                const int row0 = bm0 + wm + mi * 16 + g;
                float v0 = acc[mi][nj][0] + b0;
                float v1 = acc[mi][nj][1] + b1;
                float v2 = acc[mi][nj][2] + b0;
                float v3 = acc[mi][nj][3] + b1;
                if (RELU) {
                    v0 = fmaxf(v0, 0.f); v1 = fmaxf(v1, 0.f);
                    v2 = fmaxf(v2, 0.f); v3 = fmaxf(v3, 0.f);
                }
                if (row0 < M) {
                    *reinterpret_cast<__nv_bfloat162*>(C + (size_t)row0 * ldc + col) =
                        __floats2bfloat162_rn(v0, v1);
                }
                if (row0 + 8 < M) {
                    *reinterpret_cast<__nv_bfloat162*>(C + (size_t)(row0 + 8) * ldc + col) =
                        __floats2bfloat162_rn(v2, v3);
                }
            }
        }
    }
}

// ---------------- merged dual-CSR gather (bf16 src, bf16 dst): one warp per (set,node) ----------------
__device__ __forceinline__ float4 bf4_to_f4(uint2 u) {
    __nv_bfloat162 p0 = *reinterpret_cast<__nv_bfloat162*>(&u.x);
    __nv_bfloat162 p1 = *reinterpret_cast<__nv_bfloat162*>(&u.y);
    float2 f0 = __bfloat1622float2(p0);
    float2 f1 = __bfloat1622float2(p1);
    return make_float4(f0.x, f0.y, f1.x, f1.y);
}

__global__ __launch_bounds__(256)
void gather2_kernel(const int* __restrict__ rp1, const int* __restrict__ adj1, const float* __restrict__ dis1,
                    const int* __restrict__ rp2, const int* __restrict__ adj2, const float* __restrict__ dis2,
                    const __nv_bfloat16* __restrict__ src, const float* __restrict__ bias,
                    __nv_bfloat16* __restrict__ fin, int off1, int off2, int n) {
    int gw = (blockIdx.x * blockDim.x + threadIdx.x) >> 5;
    int lane = threadIdx.x & 31;
    if (gw >= 2 * n) return;
    const bool second = (gw >= n);
    const int node = second ? gw - n : gw;
    const int* rowptr = second ? rp2 : rp1;
    const int* adj    = second ? adj2 : adj1;
    const float* dis  = second ? dis2 : dis1;
    __nv_bfloat16* outp = fin + (second ? off2 : off1);

    int s = rowptr[node];
    int e = rowptr[node + 1];
    const __nv_bfloat16* base = src + lane * 4;
    float ax = 0.f, ay = 0.f, az = 0.f, aw = 0.f;
#pragma unroll 4
    for (int i = s; i < e; i++) {
        int r = __ldg(&adj[i]);
        float nr = __ldg(&dis[r]);
        uint2 u = *reinterpret_cast<const uint2*>(base + (size_t)r * 128);
        float4 v = bf4_to_f4(u);
        ax = fmaf(v.x, nr, ax);
        ay = fmaf(v.y, nr, ay);
        az = fmaf(v.z, nr, az);
        aw = fmaf(v.w, nr, aw);
    }
    float dc = dis[node];
    float4 b = *reinterpret_cast<const float4*>(bias + lane * 4);
    uint2 st;
    st.x = packbf(fmaf(ax, dc, b.x), fmaf(ay, dc, b.y));
    st.y = packbf(fmaf(az, dc, b.z), fmaf(aw, dc, b.w));
    *reinterpret_cast<uint2*>(outp + (size_t)node * DFIN + lane * 4) = st;
}

// ---------------- host launcher ----------------
extern "C" void kernel_launch(void* const* d_in, const int* in_sizes, int n_in,
                              void* d_out, int out_size) {
    const float* x       = (const float*)d_in[0];
    const int*   ei1     = (const int*)  d_in[1];
    const int*   ei2     = (const int*)  d_in[2];
    const float* W_lin1  = (const float*)d_in[3];
    const float* b_lin1  = (const float*)d_in[4];
    const float* W_c1    = (const float*)d_in[5];
    const float* b_c1    = (const float*)d_in[6];
    const float* W_c2    = (const float*)d_in[7];
    const float* b_c2    = (const float*)d_in[8];
    const float* W_lin2  = (const float*)d_in[9];
    const float* b_lin2  = (const float*)d_in[10];
    float* out = (float*)d_out;

    const int E1 = in_sizes[1] / 2;
    const int E2 = in_sizes[2] / 2;
    const int n  = NNODES;

    __nv_bfloat16 *p_hwh, *p_final, *p_w1, *p_wc1, *p_wc2, *p_w2;
    float *p_dis1, *p_dis2;
    int *p_cnt1, *p_cnt2, *p_rp1, *p_rp2, *p_cur1, *p_cur2, *p_adj1, *p_adj2;
    cudaGetSymbolAddress((void**)&p_hwh,    g_hwh);
    cudaGetSymbolAddress((void**)&p_final,  g_final);
    cudaGetSymbolAddress((void**)&p_w1,     g_w1);
    cudaGetSymbolAddress((void**)&p_wc1,    g_wc1);
    cudaGetSymbolAddress((void**)&p_wc2,    g_wc2);
    cudaGetSymbolAddress((void**)&p_w2,     g_w2);
    cudaGetSymbolAddress((void**)&p_dis1,   g_dis1);
    cudaGetSymbolAddress((void**)&p_dis2,   g_dis2);
    cudaGetSymbolAddress((void**)&p_cnt1,   g_cnt1);
    cudaGetSymbolAddress((void**)&p_cnt2,   g_cnt2);
    cudaGetSymbolAddress((void**)&p_rp1,    g_rowptr1);
    cudaGetSymbolAddress((void**)&p_rp2,    g_rowptr2);
    cudaGetSymbolAddress((void**)&p_cur1,   g_cursor1);
    cudaGetSymbolAddress((void**)&p_cur2,   g_cursor2);
    cudaGetSymbolAddress((void**)&p_adj1,   g_adj1);
    cudaGetSymbolAddress((void**)&p_adj2,   g_adj2);

    // lazy-init side stream + fork/join events
    static cudaStream_t s2 = nullptr;
    static cudaEvent_t evFork = nullptr, evJoin = nullptr;
    if (s2 == nullptr) {
        cudaStreamCreateWithFlags(&s2, cudaStreamNonBlocking);
        cudaEventCreateWithFlags(&evFork, cudaEventDisableTiming);
        cudaEventCreateWithFlags(&evJoin, cudaEventDisableTiming);
    }

    // ---- fork: CSR build on s2, overlapped with weight-cvt + GEMM1/GEMM2 ----
    cudaEventRecord(evFork, 0);
    cudaStreamWaitEvent(s2, evFork, 0);
    zero2_kernel<<<(n + 255) / 256, 256, 0, s2>>>(p_cnt1, p_cnt2, n);
    hist2_kernel<<<(E1 + E2 + 255) / 256, 256, 0, s2>>>(ei1, E1, p_cnt1, ei2, E2, p_cnt2);
    scan2_kernel<<<2, 1024, 0, s2>>>(p_cnt1, p_rp1, p_cur1, p_dis1, p_cnt2, p_rp2, p_cur2, p_dis2, n);
    fill2_kernel<<<(E1 + E2 + 255) / 256, 256, 0, s2>>>(ei1, E1, p_cur1, p_adj1, ei2, E2, p_cur2, p_adj2);
    cudaEventRecord(evJoin, s2);

    // ---- weights -> bf16 (tiny; main stream, ahead of GEMM1) ----
    cvt_weights_kernel<<<232, 256>>>(W_lin1, W_c1, W_c2, W_lin2, p_w1, p_wc1, p_wc2, p_w2);

    const int gy = (n + 127) / 128;  // 391
    const int gather2_grid = (2 * n * 32 + 255) / 256;

    // ---- h = relu(x @ W1 + b1) -> final[:, 0:256]  (A fp32, converted in-kernel) ----
    mma_gemm_bf16<128, true, true, true, false><<<dim3(H0 / 128, gy), 256>>>(
        x, F_IN, p_w1, b_lin1, p_final, DFIN, n, H0, F_IN);

    // ---- hw(bf16) = h @ Wc1 ----
    mma_gemm_bf16<128, false, false, false, false><<<dim3(1, gy), 256>>>(
        p_final, DFIN, p_wc1, nullptr, p_hwh, H1, n, H1, H0);

    // ---- join: gathers need CSR ----
    cudaStreamWaitEvent(0, evJoin, 0);

    // ---- layer-1 gathers -> final[:,256:384],[:,384:512] ----
    gather2_kernel<<<gather2_grid, 256>>>(p_rp1, p_adj1, p_dis1, p_rp2, p_adj2, p_dis2,
                                          p_hwh, b_c1, p_final, 256, 384, n);

    // ---- hw(bf16) = R1 @ Wc2  (R1 = final[:, 256:512]) ----
    mma_gemm_bf16<128, false, false, false, false><<<dim3(1, gy), 256>>>(
        p_final + 256, DFIN, p_wc2, nullptr, p_hwh, H2, n, H2, 2 * H1);

    // ---- layer-2 gathers -> final[:,512:640],[:,640:768] ----
    gather2_kernel<<<gather2_grid, 256>>>(p_rp1, p_adj1, p_dis1, p_rp2, p_adj2, p_dis2,
                                          p_hwh, b_c2, p_final, 512, 640, n);

    // ---- logits = final @ W2 + b2, fused log_softmax -> out ----
    mma_gemm_bf16<64, false, true, false, true><<<dim3(1, gy), 256>>>(
        p_final, DFIN, p_w2, b_lin2, out, NCLS, n, NCLS, DFIN);
}

// round 8
// speedup vs baseline: 4.0192x; 1.0406x over previous
#include <cuda_runtime.h>
#include <cuda_bf16.h>
#include <cstdint>
#include <math.h>

// ---------------- problem constants ----------------
#define NNODES 50000
#define F_IN   512
#define H0     256
#define H1     128
#define H2     128
#define NCLS   40
#define DFIN   768
#define E1MAX  800000
#define E2MAX  1600000

// ---------------- static scratch ----------------
__device__ __nv_bfloat16 g_hwh[(size_t)NNODES * H1];     // bf16 message buffer
__device__ __nv_bfloat16 g_final[(size_t)NNODES * DFIN]; // bf16 concat buffer
__device__ float g_logits[(size_t)(NNODES + 128) * NCLS]; // fp32 partial logits (padded rows)
__device__ __nv_bfloat16 g_w1[F_IN * H0];
__device__ __nv_bfloat16 g_wc1[H0 * H1];
__device__ __nv_bfloat16 g_wc2[2 * H1 * H2];
__device__ __nv_bfloat16 g_w2[DFIN * NCLS];
__device__ float g_dis1[NNODES];
__device__ float g_dis2[NNODES];
__device__ int   g_cnt1[NNODES];
__device__ int   g_cnt2[NNODES];
__device__ int   g_rowptr1[NNODES + 1];
__device__ int   g_rowptr2[NNODES + 1];
__device__ int   g_cursor1[NNODES];
__device__ int   g_cursor2[NNODES];
__device__ int   g_adj1[E1MAX];
__device__ int   g_adj2[E2MAX];

// ---------------- weight conversion fp32 -> bf16 ----------------
__global__ void cvt_weights_kernel(const float* __restrict__ w1, const float* __restrict__ wc1,
                                   const float* __restrict__ wc2, const float* __restrict__ w2,
                                   __nv_bfloat16* __restrict__ o1, __nv_bfloat16* __restrict__ oc1,
                                   __nv_bfloat16* __restrict__ oc2, __nv_bfloat16* __restrict__ o2) {
    const int S1 = F_IN * H0, S2 = H0 * H1, S3 = 2 * H1 * H2, S4 = DFIN * NCLS;
    int i = blockIdx.x * blockDim.x + threadIdx.x;
    int total = S1 + S2 + S3 + S4;
    for (; i < total; i += gridDim.x * blockDim.x) {
        if (i < S1) o1[i] = __float2bfloat16_rn(w1[i]);
        else if (i < S1 + S2) oc1[i - S1] = __float2bfloat16_rn(wc1[i - S1]);
        else if (i < S1 + S2 + S3) oc2[i - S1 - S2] = __float2bfloat16_rn(wc2[i - S1 - S2]);
        else o2[i - S1 - S2 - S3] = __float2bfloat16_rn(w2[i - S1 - S2 - S3]);
    }
}

// ---------------- CSR build ----------------
__global__ void zero2_kernel(int* __restrict__ p1, int* __restrict__ p2, int n) {
    int i = blockIdx.x * blockDim.x + threadIdx.x;
    if (i < n) { p1[i] = 0; p2[i] = 0; }
}

__global__ void hist2_kernel(const int* __restrict__ ei1, int E1, int* __restrict__ cnt1,
                             const int* __restrict__ ei2, int E2, int* __restrict__ cnt2) {
    int i = blockIdx.x * blockDim.x + threadIdx.x;
    if (i < E1) {
        atomicAdd(&cnt1[ei1[E1 + i]], 1);
    } else if (i < E1 + E2) {
        int j = i - E1;
        atomicAdd(&cnt2[ei2[E2 + j]], 1);
    }
}

__global__ __launch_bounds__(1024)
void scan2_kernel(int* __restrict__ cnt1, int* __restrict__ rp1, int* __restrict__ cur1, float* __restrict__ dis1,
                  int* __restrict__ cnt2, int* __restrict__ rp2, int* __restrict__ cur2, float* __restrict__ dis2,
                  int n) {
    const int* cnt = (blockIdx.x == 0) ? cnt1 : cnt2;
    int* rowptr    = (blockIdx.x == 0) ? rp1  : rp2;
    int* cursor    = (blockIdx.x == 0) ? cur1 : cur2;
    float* dis     = (blockIdx.x == 0) ? dis1 : dis2;
    __shared__ int part[1024];
    const int t = threadIdx.x;
    const int chunk = (n + 1023) / 1024;
    const int s0 = min(t * chunk, n);
    const int s1 = min(s0 + chunk, n);
    int sum = 0;
    for (int i = s0; i < s1; i++) sum += cnt[i];
    part[t] = sum;
    __syncthreads();
    for (int off = 1; off < 1024; off <<= 1) {
        int v = part[t];
        int o = (t >= off) ? part[t - off] : 0;
        __syncthreads();
        part[t] = v + o;
        __syncthreads();
    }
    int run = (t == 0) ? 0 : part[t - 1];
    for (int i = s0; i < s1; i++) {
        rowptr[i] = run;
        cursor[i] = run;
        int c = cnt[i];
        dis[i] = (c > 0) ? rsqrtf((float)c) : 0.f;
        run += c;
    }
    if (t == 1023) rowptr[n] = part[1023];
}

__global__ void fill2_kernel(const int* __restrict__ ei1, int E1, int* __restrict__ cur1, int* __restrict__ adj1,
                             const int* __restrict__ ei2, int E2, int* __restrict__ cur2, int* __restrict__ adj2) {
    int i = blockIdx.x * blockDim.x + threadIdx.x;
    if (i < E1) {
        int slot = atomicAdd(&cur1[ei1[E1 + i]], 1);
        adj1[slot] = ei1[i];
    } else if (i < E1 + E2) {
        int j = i - E1;
        int slot = atomicAdd(&cur2[ei2[E2 + j]], 1);
        adj2[slot] = ei2[j];
    }
}

// ---------------- helpers ----------------
__device__ __forceinline__ void mma_bf16(float* c, const uint32_t* a, uint32_t b0, uint32_t b1) {
    asm volatile(
        "mma.sync.aligned.m16n8k16.row.col.f32.bf16.bf16.f32 "
        "{%0,%1,%2,%3}, {%4,%5,%6,%7}, {%8,%9}, {%0,%1,%2,%3};"
        : "+f"(c[0]), "+f"(c[1]), "+f"(c[2]), "+f"(c[3])
        : "r"(a[0]), "r"(a[1]), "r"(a[2]), "r"(a[3]), "r"(b0), "r"(b1));
}

__device__ __forceinline__ void cp16(uint32_t saddr, const void* gaddr, int srcsz) {
    asm volatile("cp.async.cg.shared.global [%0], [%1], 16, %2;"
                 :: "r"(saddr), "l"(gaddr), "r"(srcsz));
}

__device__ __forceinline__ uint32_t packbf(float a, float b) {
    __nv_bfloat162 h = __floats2bfloat162_rn(a, b);
    return *reinterpret_cast<uint32_t*>(&h);
}

// smem bytes for the pipelined GEMM (3 stages), must match kernel layout
#define GEMM_AS_BYTES (3 * 128 * 40 * 2)
#define GEMM_SMEM(BN) (GEMM_AS_BYTES + 3 * 32 * ((BN) + 8) * 2)

// ---------------- bf16 tensor-core GEMM, 3-stage cp.async pipeline ----------------
// BM=128, BK=32, BN in {128, 64}; 8 warps; mma m16n8k16 bf16, fp32 accumulate.
// ACONV: A fp32 in gmem, converted via reg staging. OUTMODE: 0=bf16 C, 1=f32 C,
// 2=fused log_softmax (+optional fp32 preacc) -> fp32 out. Requires K/32 >= 2.
template <int BN, bool RELU, bool BIAS, bool ACONV, int OUTMODE>
__global__ __launch_bounds__(256)
void mma_gemm_bf16(const void* __restrict__ Av, int lda,
                   const __nv_bfloat16* __restrict__ B,
                   const float* __restrict__ bias,
                   const float* __restrict__ pre,
                   void* __restrict__ Cv, int ldc,
                   int M, int N, int K) {
    constexpr int MI = (BN == 128) ? 4 : 2;
    constexpr int BK = 32;
    extern __shared__ __align__(16) char smem_raw[];
    using AsT = __nv_bfloat16[128][BK + 8];
    using BsT = __nv_bfloat16[BK][BN + 8];
    AsT* As = reinterpret_cast<AsT*>(smem_raw);
    BsT* Bs = reinterpret_cast<BsT*>(smem_raw + GEMM_AS_BYTES);
    float (*Ls)[44] = reinterpret_cast<float(*)[44]>(smem_raw);

    const int tid  = threadIdx.x;
    const int lane = tid & 31;
    const int warp = tid >> 5;
    const int bm0 = blockIdx.y * 128;
    const int bn0 = blockIdx.x * BN;
    const int wm = (BN == 128) ? (warp & 1) * 64 : (warp & 3) * 32;
    const int wn = (BN == 128) ? (warp >> 1) * 32 : (warp >> 2) * 32;
    const int g  = lane >> 2;
    const int tg = lane & 3;

    float acc[MI][4][4];
#pragma unroll
    for (int i = 0; i < MI; i++)
#pragma unroll
        for (int j = 0; j < 4; j++)
#pragma unroll
            for (int q = 0; q < 4; q++) acc[i][j][q] = 0.f;

    const int aRow = tid >> 1;
    const int aEl  = (tid & 1) * 16;
    const bool aValid = (bm0 + aRow) < M;
    const __nv_bfloat16* Ah = ACONV ? nullptr : ((const __nv_bfloat16*)Av + (size_t)(bm0 + aRow) * lda + aEl);
    const float*         Af = ACONV ? ((const float*)Av + (size_t)(bm0 + aRow) * lda + aEl) : nullptr;

    const int bRow = (BN == 128) ? (tid >> 4) : (tid >> 3);
    const int bEl  = (BN == 128) ? (tid & 15) * 8 : (tid & 7) * 8;
    const int bSz  = ((bn0 + bEl) < N) ? 16 : 0;
    const __nv_bfloat16* Bptr = B + (size_t)bRow * N + bn0 + bEl;

    const int ntiles = K / BK;

    auto loadB = [&](int t, int s) {
        const int k0 = t * BK;
        uint32_t sb = (uint32_t)__cvta_generic_to_shared(&Bs[s][bRow][bEl]);
        cp16(sb, Bptr + (size_t)k0 * N, bSz);
        if (BN == 128) {
            uint32_t sb1 = (uint32_t)__cvta_generic_to_shared(&Bs[s][bRow + 16][bEl]);
            cp16(sb1, Bptr + (size_t)(k0 + 16) * N, bSz);
        }
    };
    auto loadA_cp = [&](int t, int s) {
        const int k0 = t * BK;
        uint32_t sa = (uint32_t)__cvta_generic_to_shared(&As[s][aRow][aEl]);
        cp16(sa,      Ah + k0,     aValid ? 16 : 0);
        cp16(sa + 16, Ah + k0 + 8, aValid ? 16 : 0);
    };
    float4 pa[4];
    auto ldgA = [&](int t) {
        const int k0 = t * BK;
        if (aValid) {
#pragma unroll
            for (int j = 0; j < 4; j++)
                pa[j] = *reinterpret_cast<const float4*>(Af + k0 + j * 4);
        } else {
#pragma unroll
            for (int j = 0; j < 4; j++) pa[j] = make_float4(0.f, 0.f, 0.f, 0.f);
        }
    };
    auto stsA = [&](int s) {
        uint4 u0, u1;
        u0.x = packbf(pa[0].x, pa[0].y); u0.y = packbf(pa[0].z, pa[0].w);
        u0.z = packbf(pa[1].x, pa[1].y); u0.w = packbf(pa[1].z, pa[1].w);
        u1.x = packbf(pa[2].x, pa[2].y); u1.y = packbf(pa[2].z, pa[2].w);
        u1.z = packbf(pa[3].x, pa[3].y); u1.w = packbf(pa[3].z, pa[3].w);
        uint4* d = reinterpret_cast<uint4*>(&As[s][aRow][aEl]);
        d[0] = u0; d[1] = u1;
    };

    // ---- prologue: stages 0,1 ----
    if (ACONV) ldgA(0);
    loadB(0, 0);
    if (!ACONV) loadA_cp(0, 0);
    asm volatile("cp.async.commit_group;");
    if (ACONV) { stsA(0); ldgA(1); }
    loadB(1, 1);
    if (!ACONV) loadA_cp(1, 1);
    asm volatile("cp.async.commit_group;");
    if (ACONV) stsA(1);

    const int lmA_row = wm + (lane & 15);
    const int lmA_col = (lane >> 4) * 8;
    const int lmB_row = lane & 15;
    const int lmB_col = (lane >> 4) * 8;

    for (int t = 0; t < ntiles; t++) {
        asm volatile("cp.async.wait_group 1;" ::: "memory");
        __syncthreads();
        const int s  = t % 3;
        const int sn = (t + 2) % 3;
        const bool next2 = (t + 2 < ntiles);
        if (next2) {
            loadB(t + 2, sn);
            if (!ACONV) loadA_cp(t + 2, sn);
        }
        asm volatile("cp.async.commit_group;");
        if (next2 && ACONV) ldgA(t + 2);

#pragma unroll
        for (int kk = 0; kk < BK; kk += 16) {
            uint32_t af[MI][4];
#pragma unroll
            for (int mi = 0; mi < MI; mi++) {
                uint32_t saddr = (uint32_t)__cvta_generic_to_shared(
                    &As[s][lmA_row + mi * 16][kk + lmA_col]);
                asm volatile("ldmatrix.sync.aligned.m8n8.x4.shared.b16 {%0,%1,%2,%3}, [%4];"
                             : "=r"(af[mi][0]), "=r"(af[mi][1]), "=r"(af[mi][2]), "=r"(af[mi][3])
                             : "r"(saddr));
            }
            uint32_t bf[2][4];
#pragma unroll
            for (int nj2 = 0; nj2 < 2; nj2++) {
                uint32_t saddr = (uint32_t)__cvta_generic_to_shared(
                    &Bs[s][kk + lmB_row][wn + nj2 * 16 + lmB_col]);
                asm volatile("ldmatrix.sync.aligned.m8n8.x4.trans.shared.b16 {%0,%1,%2,%3}, [%4];"
                             : "=r"(bf[nj2][0]), "=r"(bf[nj2][1]), "=r"(bf[nj2][2]), "=r"(bf[nj2][3])
                             : "r"(saddr));
            }
#pragma unroll
            for (int nj = 0; nj < 4; nj++) {
                uint32_t b0 = bf[nj >> 1][(nj & 1) * 2];
                uint32_t b1 = bf[nj >> 1][(nj & 1) * 2 + 1];
#pragma unroll
                for (int mi = 0; mi < MI; mi++) {
                    mma_bf16(acc[mi][nj], af[mi], b0, b1);
                }
            }
        }
        if (next2 && ACONV) stsA(sn);
    }

    if (OUTMODE == 2) {
        __syncthreads();
#pragma unroll
        for (int nj = 0; nj < 4; nj++) {
            const int col = bn0 + wn + nj * 8 + tg * 2;
            if (col >= NCLS) continue;
            float b0 = bias[col], b1 = bias[col + 1];
#pragma unroll
            for (int mi = 0; mi < MI; mi++) {
                const int r0 = wm + mi * 16 + g;
                float p00 = 0.f, p01 = 0.f, p10 = 0.f, p11 = 0.f;
                if (pre) {
                    const float* pr = pre + (size_t)(bm0 + r0) * NCLS + col;
                    p00 = pr[0]; p01 = pr[1];
                    p10 = pr[8 * NCLS]; p11 = pr[8 * NCLS + 1];
                }
                Ls[r0][col]         = acc[mi][nj][0] + b0 + p00;
                Ls[r0][col + 1]     = acc[mi][nj][1] + b1 + p01;
                Ls[r0 + 8][col]     = acc[mi][nj][2] + b0 + p10;
                Ls[r0 + 8][col + 1] = acc[mi][nj][3] + b1 + p11;
            }
        }
        __syncthreads();
        float* O = (float*)Cv;
#pragma unroll
        for (int rr = 0; rr < 16; rr++) {
            const int r = warp * 16 + rr;
            const int grow = bm0 + r;
            if (grow >= M) break;
            float v0 = Ls[r][lane];
            float v1 = (lane < NCLS - 32) ? Ls[r][32 + lane] : -INFINITY;
            float m = fmaxf(v0, v1);
#pragma unroll
            for (int o = 16; o > 0; o >>= 1) m = fmaxf(m, __shfl_xor_sync(0xffffffffu, m, o));
            float sum = expf(v0 - m) + ((lane < NCLS - 32) ? expf(v1 - m) : 0.f);
#pragma unroll
            for (int o = 16; o > 0; o >>= 1) sum += __shfl_xor_sync(0xffffffffu, sum, o);
            float ls = logf(sum);
            O[(size_t)grow * NCLS + lane] = v0 - m - ls;
            if (lane < NCLS - 32) O[(size_t)grow * NCLS + 32 + lane] = v1 - m - ls;
        }
    } else {
#pragma unroll
        for (int nj = 0; nj < 4; nj++) {
            const int col = bn0 + wn + nj * 8 + tg * 2;
            if (col >= N) continue;
            float b0 = 0.f, b1 = 0.f;
            if (BIAS) { b0 = bias[col]; b1 = bias[col + 1]; }
#pragma unroll
            for (int mi = 0; mi < MI; mi++) {
                const int row0 = bm0 + wm + mi * 16 + g;
                float v0 = acc[mi][nj][0] + b0;
                float v1 = acc[mi][nj][1] + b1;
                float v2 = acc[mi][nj][2] + b0;
                float v3 = acc[mi][nj][3] + b1;
                if (RELU) {
                    v0 = fmaxf(v0, 0.f); v1 = fmaxf(v1, 0.f);
                    v2 = fmaxf(v2, 0.f); v3 = fmaxf(v3, 0.f);
                }
                if (OUTMODE == 0) {
                    __nv_bfloat16* C = (__nv_bfloat16*)Cv;
                    if (row0 < M) {
                        *reinterpret_cast<__nv_bfloat162*>(C + (size_t)row0 * ldc + col) =
                            __floats2bfloat162_rn(v0, v1);
                    }
                    if (row0 + 8 < M) {
                        *reinterpret_cast<__nv_bfloat162*>(C + (size_t)(row0 + 8) * ldc + col) =
                            __floats2bfloat162_rn(v2, v3);
                    }
                } else {
                    float* C = (float*)Cv;
                    if (row0 < M) {
                        *reinterpret_cast<float2*>(C + (size_t)row0 * ldc + col) = make_float2(v0, v1);
                    }
                    if (row0 + 8 < M) {
                        *reinterpret_cast<float2*>(C + (size_t)(row0 + 8) * ldc + col) = make_float2(v2, v3);
                    }
                }
            }
        }
    }
}

// ---------------- merged dual-CSR gather (bf16 src, bf16 dst), 2-way unrolled ----------------
__device__ __forceinline__ float4 bf4_to_f4(uint2 u) {
    __nv_bfloat162 p0 = *reinterpret_cast<__nv_bfloat162*>(&u.x);
    __nv_bfloat162 p1 = *reinterpret_cast<__nv_bfloat162*>(&u.y);
    float2 f0 = __bfloat1622float2(p0);
    float2 f1 = __bfloat1622float2(p1);
    return make_float4(f0.x, f0.y, f1.x, f1.y);
}

__global__ __launch_bounds__(256)
void gather2_kernel(const int* __restrict__ rp1, const int* __restrict__ adj1, const float* __restrict__ dis1,
                    const int* __restrict__ rp2, const int* __restrict__ adj2, const float* __restrict__ dis2,
                    const __nv_bfloat16* __restrict__ src, const float* __restrict__ bias,
                    __nv_bfloat16* __restrict__ fin, int off1, int off2, int n) {
    int gw = (blockIdx.x * blockDim.x + threadIdx.x) >> 5;
    int lane = threadIdx.x & 31;
    if (gw >= 2 * n) return;
    const bool second = (gw >= n);
    const int node = second ? gw - n : gw;
    const int* rowptr = second ? rp2 : rp1;
    const int* adj    = second ? adj2 : adj1;
    const float* dis  = second ? dis2 : dis1;
    __nv_bfloat16* outp = fin + (second ? off2 : off1);

    int s = rowptr[node];
    int e = rowptr[node + 1];
    const __nv_bfloat16* base = src + lane * 4;
    float ax = 0.f, ay = 0.f, az = 0.f, aw = 0.f;
    float bx = 0.f, by = 0.f, bz = 0.f, bw = 0.f;
    int i = s;
#pragma unroll 2
    for (; i + 2 <= e; i += 2) {
        int r0 = __ldg(&adj[i]);
        int r1 = __ldg(&adj[i + 1]);
        float n0 = __ldg(&dis[r0]);
        float n1 = __ldg(&dis[r1]);
        uint2 u0 = *reinterpret_cast<const uint2*>(base + (size_t)r0 * 128);
        uint2 u1 = *reinterpret_cast<const uint2*>(base + (size_t)r1 * 128);
        float4 v0 = bf4_to_f4(u0);
        float4 v1 = bf4_to_f4(u1);
        ax = fmaf(v0.x, n0, ax); ay = fmaf(v0.y, n0, ay);
        az = fmaf(v0.z, n0, az); aw = fmaf(v0.w, n0, aw);
        bx = fmaf(v1.x, n1, bx); by = fmaf(v1.y, n1, by);
        bz = fmaf(v1.z, n1, bz); bw = fmaf(v1.w, n1, bw);
    }
    if (i < e) {
        int r0 = __ldg(&adj[i]);
        float n0 = __ldg(&dis[r0]);
        uint2 u0 = *reinterpret_cast<const uint2*>(base + (size_t)r0 * 128);
        float4 v0 = bf4_to_f4(u0);
        ax = fmaf(v0.x, n0, ax); ay = fmaf(v0.y, n0, ay);
        az = fmaf(v0.z, n0, az); aw = fmaf(v0.w, n0, aw);
    }
    ax += bx; ay += by; az += bz; aw += bw;
    float dc = dis[node];
    float4 b = *reinterpret_cast<const float4*>(bias + lane * 4);
    uint2 st;
    st.x = packbf(fmaf(ax, dc, b.x), fmaf(ay, dc, b.y));
    st.y = packbf(fmaf(az, dc, b.z), fmaf(aw, dc, b.w));
    *reinterpret_cast<uint2*>(outp + (size_t)node * DFIN + lane * 4) = st;
}

// ---------------- host launcher ----------------
extern "C" void kernel_launch(void* const* d_in, const int* in_sizes, int n_in,
                              void* d_out, int out_size) {
    const float* x       = (const float*)d_in[0];
    const int*   ei1     = (const int*)  d_in[1];
    const int*   ei2     = (const int*)  d_in[2];
    const float* W_lin1  = (const float*)d_in[3];
    const float* b_lin1  = (const float*)d_in[4];
    const float* W_c1    = (const float*)d_in[5];
    const float* b_c1    = (const float*)d_in[6];
    const float* W_c2    = (const float*)d_in[7];
    const float* b_c2    = (const float*)d_in[8];
    const float* W_lin2  = (const float*)d_in[9];
    const float* b_lin2  = (const float*)d_in[10];
    float* out = (float*)d_out;

    const int E1 = in_sizes[1] / 2;
    const int E2 = in_sizes[2] / 2;
    const int n  = NNODES;

    __nv_bfloat16 *p_hwh, *p_final, *p_w1, *p_wc1, *p_wc2, *p_w2;
    float *p_logits, *p_dis1, *p_dis2;
    int *p_cnt1, *p_cnt2, *p_rp1, *p_rp2, *p_cur1, *p_cur2, *p_adj1, *p_adj2;
    cudaGetSymbolAddress((void**)&p_hwh,    g_hwh);
    cudaGetSymbolAddress((void**)&p_final,  g_final);
    cudaGetSymbolAddress((void**)&p_logits, g_logits);
    cudaGetSymbolAddress((void**)&p_w1,     g_w1);
    cudaGetSymbolAddress((void**)&p_wc1,    g_wc1);
    cudaGetSymbolAddress((void**)&p_wc2,    g_wc2);
    cudaGetSymbolAddress((void**)&p_w2,     g_w2);
    cudaGetSymbolAddress((void**)&p_dis1,   g_dis1);
    cudaGetSymbolAddress((void**)&p_dis2,   g_dis2);
    cudaGetSymbolAddress((void**)&p_cnt1,   g_cnt1);
    cudaGetSymbolAddress((void**)&p_cnt2,   g_cnt2);
    cudaGetSymbolAddress((void**)&p_rp1,    g_rowptr1);
    cudaGetSymbolAddress((void**)&p_rp2,    g_rowptr2);
    cudaGetSymbolAddress((void**)&p_cur1,   g_cursor1);
    cudaGetSymbolAddress((void**)&p_cur2,   g_cursor2);
    cudaGetSymbolAddress((void**)&p_adj1,   g_adj1);
    cudaGetSymbolAddress((void**)&p_adj2,   g_adj2);

    // lazy init: side stream, events, dynamic-smem attributes (first call is uncaptured)
    static cudaStream_t s2 = nullptr;
    static cudaEvent_t evFork = nullptr, evJoin = nullptr, evG1 = nullptr, evP = nullptr;
    if (s2 == nullptr) {
        cudaStreamCreateWithFlags(&s2, cudaStreamNonBlocking);
        cudaEventCreateWithFlags(&evFork, cudaEventDisableTiming);
        cudaEventCreateWithFlags(&evJoin, cudaEventDisableTiming);
        cudaEventCreateWithFlags(&evG1,   cudaEventDisableTiming);
        cudaEventCreateWithFlags(&evP,    cudaEventDisableTiming);
        cudaFuncSetAttribute(mma_gemm_bf16<128, true,  true,  true,  0>,
                             cudaFuncAttributeMaxDynamicSharedMemorySize, GEMM_SMEM(128));
        cudaFuncSetAttribute(mma_gemm_bf16<128, false, false, false, 0>,
                             cudaFuncAttributeMaxDynamicSharedMemorySize, GEMM_SMEM(128));
        cudaFuncSetAttribute(mma_gemm_bf16<64,  false, false, false, 1>,
                             cudaFuncAttributeMaxDynamicSharedMemorySize, GEMM_SMEM(64));
        cudaFuncSetAttribute(mma_gemm_bf16<64,  false, true,  false, 2>,
                             cudaFuncAttributeMaxDynamicSharedMemorySize, GEMM_SMEM(64));
    }

    // ---- fork: CSR build on s2, overlapped with weight-cvt + GEMM1/GEMM2 ----
    cudaEventRecord(evFork, 0);
    cudaStreamWaitEvent(s2, evFork, 0);
    zero2_kernel<<<(n + 255) / 256, 256, 0, s2>>>(p_cnt1, p_cnt2, n);
    hist2_kernel<<<(E1 + E2 + 255) / 256, 256, 0, s2>>>(ei1, E1, p_cnt1, ei2, E2, p_cnt2);
    scan2_kernel<<<2, 1024, 0, s2>>>(p_cnt1, p_rp1, p_cur1, p_dis1, p_cnt2, p_rp2, p_cur2, p_dis2, n);
    fill2_kernel<<<(E1 + E2 + 255) / 256, 256, 0, s2>>>(ei1, E1, p_cur1, p_adj1, ei2, E2, p_cur2, p_adj2);
    cudaEventRecord(evJoin, s2);

    // ---- weights -> bf16 (tiny; main stream) ----
    cvt_weights_kernel<<<232, 256>>>(W_lin1, W_c1, W_c2, W_lin2, p_w1, p_wc1, p_wc2, p_w2);

    const int gy = (n + 127) / 128;  // 391
    const int gather2_grid = (2 * n * 32 + 255) / 256;

    // ---- h = relu(x @ W1 + b1) -> final[:, 0:256]  (A fp32, in-kernel cvt) ----
    mma_gemm_bf16<128, true, true, true, 0><<<dim3(H0 / 128, gy), 256, GEMM_SMEM(128)>>>(
        x, F_IN, p_w1, b_lin1, nullptr, p_final, DFIN, n, H0, F_IN);

    // ---- hw(bf16) = h @ Wc1 ----
    mma_gemm_bf16<128, false, false, false, 0><<<dim3(1, gy), 256, GEMM_SMEM(128)>>>(
        p_final, DFIN, p_wc1, nullptr, nullptr, p_hwh, H1, n, H1, H0);

    // ---- join: gathers need CSR ----
    cudaStreamWaitEvent(0, evJoin, 0);

    // ---- layer-1 gathers -> final[:,256:384],[:,384:512] ----
    gather2_kernel<<<gather2_grid, 256>>>(p_rp1, p_adj1, p_dis1, p_rp2, p_adj2, p_dis2,
                                          p_hwh, b_c1, p_final, 256, 384, n);
    cudaEventRecord(evG1, 0);

    // ---- side stream: partial logits = final[:,0:512] @ W2[0:512,:]  (overlaps GEMM3+gather2) ----
    cudaStreamWaitEvent(s2, evG1, 0);
    mma_gemm_bf16<64, false, false, false, 1><<<dim3(1, gy), 256, GEMM_SMEM(64), s2>>>(
        p_final, DFIN, p_w2, nullptr, nullptr, p_logits, NCLS, n, NCLS, 512);
    cudaEventRecord(evP, s2);

    // ---- hw(bf16) = R1 @ Wc2  (R1 = final[:, 256:512]) ----
    mma_gemm_bf16<128, false, false, false, 0><<<dim3(1, gy), 256, GEMM_SMEM(128)>>>(
        p_final + 256, DFIN, p_wc2, nullptr, nullptr, p_hwh, H2, n, H2, 2 * H1);

    // ---- layer-2 gathers -> final[:,512:640],[:,640:768] ----
    gather2_kernel<<<gather2_grid, 256>>>(p_rp1, p_adj1, p_dis1, p_rp2, p_adj2, p_dis2,
                                          p_hwh, b_c2, p_final, 512, 640, n);

    // ---- final: logits += final[:,512:768] @ W2[512:768,:] + b2, fused log_softmax -> out ----
    cudaStreamWaitEvent(0, evP, 0);
    mma_gemm_bf16<64, false, true, false, 2><<<dim3(1, gy), 256, GEMM_SMEM(64)>>>(
        p_final + 512, DFIN, p_w2 + 512 * NCLS, b_lin2, p_logits, out, NCLS, n, NCLS, 256);
}